// round 8
// baseline (speedup 1.0000x reference)
#include <cuda_runtime.h>

// ---------------------------------------------------------------------------
// MPNEncoder: message-passing network, DEPTH=6, H=128.  (fp32 FFMA2 path —
// tcgen05 is unavailable: harness compiles via virtual arch compute_103.)
//
//   inp        = init_messages @ W_i                      (once)
//   attnei[a]  = sum_j attfea[a2attached[a,j]]            (once)
//   bias2[b]   = inp[b] + (attnei[b2a[b]] - attfea[b2a[b2revb[b]]]) @ W_h[128:]
//   msg        = relu(inp)
//   5x: nei[a] = sum_j msg[a2nei[a,j]]
//       msg    = relu(bias2 + (nei[b2a] - msg[b2revb]) @ W_h[:128])
//
// GEMMs: fma.rn.f32x2 with lanes paired over K.
// 256 threads/CTA, thread tile 8 rows x 8 cols (acc = 128 regs -> ptxas gets
// a 256-reg budget for deep LDS pipelining).  CTA tile 128x128, full K.
// ---------------------------------------------------------------------------

constexpr int NBb  = 500000;
constexpr int NAa  = 250000;
constexpr int DMSG = 165;
constexpr int DATT = 151;
constexpr int HH   = 128;

__device__ float g_bias2 [(size_t)NBb * HH];
__device__ float g_msg0  [(size_t)NBb * HH];
__device__ float g_msg1  [(size_t)NBb * HH];
__device__ float g_nei   [(size_t)NAa * HH];
__device__ float g_attnei[(size_t)NAa * DATT];

typedef unsigned long long u64;

__device__ __forceinline__ u64 pack2(float lo, float hi) {
    u64 d;
    asm("mov.b64 %0, {%1, %2};" : "=l"(d) : "f"(lo), "f"(hi));
    return d;
}
__device__ __forceinline__ void unpack2(u64 v, float& lo, float& hi) {
    asm("mov.b64 {%0, %1}, %2;" : "=f"(lo), "=f"(hi) : "l"(v));
}
__device__ __forceinline__ void fma2(u64& d, u64 a, u64 b) {
    asm("fma.rn.f32x2 %0, %1, %2, %0;" : "+l"(d) : "l"(a), "l"(b));
}

// ---------------------------------------------------------------------------
// Core k-paired GEMM loop, 8x8 thread tile.
// sA: float[128][PITCHF] (PITCHF even); sB: u64[KK][128] with
// sB[kk][c] = (B[2kk][c], B[2kk+1][c]).
// Thread (tx 0..15, ty 0..15): rows ty*8..+7, cols {tx + 16j}, j=0..7.
// ---------------------------------------------------------------------------
template<int KK, int PITCHF>
__device__ __forceinline__ void gemm_kpair8(const float* __restrict__ sA,
                                            const u64* __restrict__ sB,
                                            u64 (&acc)[8][8], int ty, int tx) {
    const float* pa = sA + ty * 8 * PITCHF;
    const u64*   pb = sB + tx;
    #pragma unroll 2
    for (int kk = 0; kk < KK; ++kk) {
        u64 a[8], b[8];
        #pragma unroll
        for (int i = 0; i < 8; ++i)
            a[i] = *(const u64*)(pa + i * PITCHF + 2 * kk);
        const u64* pk = pb + (size_t)kk * HH;
        #pragma unroll
        for (int j = 0; j < 8; ++j) b[j] = pk[16 * j];
        #pragma unroll
        for (int i = 0; i < 8; ++i)
            #pragma unroll
            for (int j = 0; j < 8; ++j)
                fma2(acc[i][j], a[i], b[j]);
    }
}

__device__ __forceinline__ void zero_acc8(u64 (&acc)[8][8]) {
    #pragma unroll
    for (int i = 0; i < 8; ++i)
        #pragma unroll
        for (int j = 0; j < 8; ++j) acc[i][j] = 0ull;
}

// ---------------------------------------------------------------------------
// Kernel 1: inp = A @ W_i ; bias_out = inp ; msg_out = relu(inp).  K=165.
// ---------------------------------------------------------------------------
__global__ void __launch_bounds__(256, 1) k_gemm_wi(
    const float* __restrict__ A, const float* __restrict__ W,
    float* __restrict__ bias_out, float* __restrict__ msg_out)
{
    constexpr int KK = 83, PITCHF = 166;
    extern __shared__ float sm[];
    float* sA = sm;                                  // [128][166]
    u64*   sB = (u64*)(sm + 128 * PITCHF);           // [83][128]
    const int tid = threadIdx.x;

    for (int i = tid; i < KK * HH; i += 256) {
        int kk = i >> 7, c = i & 127;
        float lo = W[(2 * kk) * HH + c];
        float hi = (2 * kk + 1 < DMSG) ? W[(2 * kk + 1) * HH + c] : 0.f;
        sB[i] = pack2(lo, hi);
    }

    const long row0 = (long)blockIdx.x * 128;
    const int warp = tid >> 5, lane = tid & 31;
    for (int r = warp; r < 128; r += 8) {
        long b = row0 + r;
        bool valid = b < NBb;
        const float* src = A + (long)(valid ? b : 0) * DMSG;
        float* d = sA + r * PITCHF;
        for (int c = lane; c < PITCHF; c += 32)
            d[c] = (valid && c < DMSG) ? src[c] : 0.f;
    }
    __syncthreads();

    const int tx = tid & 15, ty = tid >> 4;
    u64 acc[8][8];
    zero_acc8(acc);
    gemm_kpair8<KK, PITCHF>(sA, sB, acc, ty, tx);

    #pragma unroll
    for (int i = 0; i < 8; ++i) {
        long r = row0 + ty * 8 + i;
        if (r < NBb) {
            #pragma unroll
            for (int j = 0; j < 8; ++j) {
                float lo, hi;
                unpack2(acc[i][j], lo, hi);
                float v = lo + hi;
                int c = tx + 16 * j;
                bias_out[r * HH + c] = v;
                msg_out[r * HH + c]  = fmaxf(v, 0.f);
            }
        }
    }
}

// ---------------------------------------------------------------------------
// Kernel 2: attnei[a] = sum_j attfea[a2attached[a,j]]   (warp per atom)
// ---------------------------------------------------------------------------
__global__ void __launch_bounds__(256) k_att_agg(
    const float* __restrict__ attfea, const int* __restrict__ a2att,
    float* __restrict__ attnei)
{
    const int warp = threadIdx.x >> 5, lane = threadIdx.x & 31;
    const int a = blockIdx.x * 8 + warp;
    if (a >= NAa) return;

    int idx[6];
    #pragma unroll
    for (int j = 0; j < 6; ++j) idx[j] = a2att[a * 6 + j];

    float acc[5] = {0.f, 0.f, 0.f, 0.f, 0.f};
    #pragma unroll
    for (int j = 0; j < 6; ++j) {
        const float* p = attfea + (long)idx[j] * DATT;
        #pragma unroll
        for (int t = 0; t < 5; ++t) {
            int c = t * 32 + lane;
            if (c < DATT) acc[t] += p[c];
        }
    }
    float* o = attnei + (long)a * DATT;
    #pragma unroll
    for (int t = 0; t < 5; ++t) {
        int c = t * 32 + lane;
        if (c < DATT) o[c] = acc[t];
    }
}

// ---------------------------------------------------------------------------
// Kernel 3: bias2 += (attnei[b2a[b]] - attfea[b2a[b2revb[b]]]) @ W_h[128:279]
// K = 151 -> 76 pairs.
// ---------------------------------------------------------------------------
__global__ void __launch_bounds__(256, 1) k_gemm_att(
    const float* __restrict__ attnei, const float* __restrict__ attfea,
    const float* __restrict__ Wh_att, const int* __restrict__ b2a,
    const int* __restrict__ b2revb, float* __restrict__ bias)
{
    constexpr int KK = 76, PITCHF = 152;
    extern __shared__ float sm[];
    float* sA = sm;                                  // [128][152]
    u64*   sB = (u64*)(sm + 128 * PITCHF);           // [76][128]
    const int tid = threadIdx.x;

    for (int i = tid; i < KK * HH; i += 256) {
        int kk = i >> 7, c = i & 127;
        float lo = Wh_att[(2 * kk) * HH + c];
        float hi = (2 * kk + 1 < DATT) ? Wh_att[(2 * kk + 1) * HH + c] : 0.f;
        sB[i] = pack2(lo, hi);
    }

    const long row0 = (long)blockIdx.x * 128;
    const int warp = tid >> 5, lane = tid & 31;
    for (int r = warp; r < 128; r += 8) {
        long b = row0 + r;
        bool valid = b < NBb;
        int ia = 0, ir = 0;
        if (valid) { ia = b2a[b]; ir = b2a[b2revb[b]]; }
        const float* pa = attnei + (long)ia * DATT;
        const float* pr = attfea + (long)ir * DATT;
        float* d = sA + r * PITCHF;
        for (int c = lane; c < PITCHF; c += 32)
            d[c] = (valid && c < DATT) ? (pa[c] - pr[c]) : 0.f;
    }
    __syncthreads();

    const int tx = tid & 15, ty = tid >> 4;
    u64 acc[8][8];
    zero_acc8(acc);
    gemm_kpair8<KK, PITCHF>(sA, sB, acc, ty, tx);

    #pragma unroll
    for (int i = 0; i < 8; ++i) {
        long r = row0 + ty * 8 + i;
        if (r < NBb) {
            #pragma unroll
            for (int j = 0; j < 8; ++j) {
                float lo, hi;
                unpack2(acc[i][j], lo, hi);
                int c = tx + 16 * j;
                bias[r * HH + c] += lo + hi;
            }
        }
    }
}

// ---------------------------------------------------------------------------
// Kernel 4: nei[a] = sum_j msg[a2nei[a,j]]   (warp per atom, float4 lanes)
// ---------------------------------------------------------------------------
__global__ void __launch_bounds__(256) k_nei_agg(
    const float* __restrict__ msg, const int* __restrict__ a2nei,
    float* __restrict__ nei)
{
    const int warp = threadIdx.x >> 5, lane = threadIdx.x & 31;
    const int a = blockIdx.x * 8 + warp;
    if (a >= NAa) return;

    int idx[6];
    #pragma unroll
    for (int j = 0; j < 6; ++j) idx[j] = a2nei[a * 6 + j];

    float4 acc = make_float4(0.f, 0.f, 0.f, 0.f);
    #pragma unroll
    for (int j = 0; j < 6; ++j) {
        float4 v = *(const float4*)(msg + (long)idx[j] * HH + lane * 4);
        acc.x += v.x; acc.y += v.y; acc.z += v.z; acc.w += v.w;
    }
    *(float4*)(nei + (long)a * HH + lane * 4) = acc;
}

// ---------------------------------------------------------------------------
// Kernel 5: msg_out = relu(bias2 + (nei[b2a] - msg_in[b2revb]) @ W_h[:128])
// K = 128 -> 64 pairs.
// ---------------------------------------------------------------------------
__global__ void __launch_bounds__(256, 1) k_gemm_msg(
    const float* __restrict__ nei, const float* __restrict__ msg_in,
    const float* __restrict__ Wh, const int* __restrict__ b2a,
    const int* __restrict__ b2revb, const float* __restrict__ bias,
    float* __restrict__ msg_out)
{
    constexpr int KK = 64, PITCHF = 130;
    extern __shared__ float sm[];
    float* sA = sm;                                  // [128][130]
    u64*   sB = (u64*)(sm + 128 * PITCHF);           // [64][128]
    const int tid = threadIdx.x;

    for (int i = tid; i < KK * HH; i += 256) {
        int kk = i >> 7, c = i & 127;
        sB[i] = pack2(Wh[(2 * kk) * HH + c], Wh[(2 * kk + 1) * HH + c]);
    }

    const long row0 = (long)blockIdx.x * 128;
    const int warp = tid >> 5, lane = tid & 31;
    for (int r = warp; r < 128; r += 8) {
        long b = row0 + r;
        bool valid = b < NBb;
        int ia = valid ? b2a[b] : 0;
        int ib = valid ? b2revb[b] : 0;
        float4 x = *(const float4*)(nei + (long)ia * HH + lane * 4);
        float4 y = *(const float4*)(msg_in + (long)ib * HH + lane * 4);
        float* d = sA + r * PITCHF + lane * 4;
        d[0] = valid ? (x.x - y.x) : 0.f;
        d[1] = valid ? (x.y - y.y) : 0.f;
        d[2] = valid ? (x.z - y.z) : 0.f;
        d[3] = valid ? (x.w - y.w) : 0.f;
    }
    __syncthreads();

    const int tx = tid & 15, ty = tid >> 4;
    u64 acc[8][8];
    zero_acc8(acc);
    gemm_kpair8<KK, PITCHF>(sA, sB, acc, ty, tx);

    #pragma unroll
    for (int i = 0; i < 8; ++i) {
        long r = row0 + ty * 8 + i;
        if (r < NBb) {
            #pragma unroll
            for (int j = 0; j < 8; ++j) {
                float lo, hi;
                unpack2(acc[i][j], lo, hi);
                int c = tx + 16 * j;
                msg_out[r * HH + c] = fmaxf(bias[r * HH + c] + lo + hi, 0.f);
            }
        }
    }
}

// Dummy: shifts launch index so ncu (-s 5 -c 1) profiles the msg GEMM (#6).
__global__ void k_dummy(float* p) { if (threadIdx.x == 0) p[0] = 0.f; }

// ---------------------------------------------------------------------------
// Launch
// ---------------------------------------------------------------------------
extern "C" void kernel_launch(void* const* d_in, const int* in_sizes, int n_in,
                              void* d_out, int out_size) {
    (void)in_sizes; (void)n_in; (void)out_size;

    const float* init_messages = (const float*)d_in[0];
    const float* attfea        = (const float*)d_in[1];
    const float* W_i           = (const float*)d_in[2];
    const float* W_h           = (const float*)d_in[3];  // [279][128]
    const int*   a2nei         = (const int*)d_in[4];
    const int*   a2att         = (const int*)d_in[5];
    const int*   b2a           = (const int*)d_in[6];
    const int*   b2revb        = (const int*)d_in[7];
    float*       out           = (float*)d_out;

    constexpr int SMEM_WI  = 128 * 166 * 4 + 83 * 128 * 8;   // 169,984
    constexpr int SMEM_ATT = 128 * 152 * 4 + 76 * 128 * 8;   // 155,648
    constexpr int SMEM_MSG = 128 * 130 * 4 + 64 * 128 * 8;   // 132,096

    cudaFuncSetAttribute(k_gemm_wi,  cudaFuncAttributeMaxDynamicSharedMemorySize, SMEM_WI);
    cudaFuncSetAttribute(k_gemm_att, cudaFuncAttributeMaxDynamicSharedMemorySize, SMEM_ATT);
    cudaFuncSetAttribute(k_gemm_msg, cudaFuncAttributeMaxDynamicSharedMemorySize, SMEM_MSG);

    float *bias, *m0, *m1, *nei, *attnei;
    cudaGetSymbolAddress((void**)&bias,   g_bias2);
    cudaGetSymbolAddress((void**)&m0,     g_msg0);
    cudaGetSymbolAddress((void**)&m1,     g_msg1);
    cudaGetSymbolAddress((void**)&nei,    g_nei);
    cudaGetSymbolAddress((void**)&attnei, g_attnei);

    const int gb = (NBb + 127) / 128;   // 3907
    const int ga = NAa / 8;             // 31250

    k_dummy<<<1, 32>>>(nei);                                     // launch 1

    // Loop-invariant precompute
    k_att_agg<<<ga, 256>>>(attfea, a2att, attnei);               // 2
    k_gemm_wi<<<gb, 256, SMEM_WI>>>(init_messages, W_i, bias, m0);   // 3
    k_gemm_att<<<gb, 256, SMEM_ATT>>>(attnei, attfea, W_h + HH * HH,
                                      b2a, b2revb, bias);        // 4

    // 5 message-passing iterations (DEPTH-1), ping-pong buffers
    float* cur = m0;
    float* nxt = m1;
    for (int it = 0; it < 5; ++it) {
        k_nei_agg<<<ga, 256>>>(cur, a2nei, nei);                 // 5, 7, ...
        float* o = (it == 4) ? out : nxt;
        k_gemm_msg<<<gb, 256, SMEM_MSG>>>(nei, cur, W_h, b2a, b2revb, bias, o);  // 6 <- profiled
        float* t = cur; cur = nxt; nxt = t;
    }
}

// round 9
// speedup vs baseline: 2.0866x; 2.0866x over previous
#include <cuda_runtime.h>
#include <cstdint>

// ---------------------------------------------------------------------------
// MPNEncoder, DEPTH=6, H=128 — bf16 hi/lo split GEMMs on the legacy HMMA path
// (mma.sync.m16n8k16.bf16; tcgen05 is PTX-gated off under compute_103).
//
//   inp        = init_messages @ W_i                       (once)   [MODE 0]
//   attnei[a]  = sum_j attfea[a2attached[a,j]]             (once)
//   bias2[b]   = inp[b] + (attnei[b2a] - attfea[b2a_rev]) @ W_h[128:]  [MODE 1]
//   msg        = relu(inp)
//   5x: nei[a] = sum_j msg[a2nei[a,j]]
//       msg    = relu(bias2 + (nei[b2a] - msg[b2revb]) @ W_h[:128])    [MODE 2]
//
// Split: v = hi (fp32 with low 16 mantissa bits zeroed -> exact bf16) + lo
// (bf16 of exact residual).  D = Ahi*Bhi + Ahi*Blo + Alo*Bhi, fp32 accum.
// ---------------------------------------------------------------------------

constexpr int NBb  = 500000;
constexpr int NAa  = 250000;
constexpr int DMSG = 165;
constexpr int DATT = 151;
constexpr int HH   = 128;

__device__ float g_bias2 [(size_t)NBb * HH];
__device__ float g_msg0  [(size_t)NBb * HH];
__device__ float g_msg1  [(size_t)NBb * HH];
__device__ float g_nei   [(size_t)NAa * HH];
__device__ float g_attnei[(size_t)NAa * DATT];

typedef unsigned int u32;

__device__ __forceinline__ u32 smem_u32(const void* p) {
    u32 a;
    asm("{ .reg .u64 t; cvta.to.shared.u64 t, %1; cvt.u32.u64 %0, t; }"
        : "=r"(a) : "l"(p));
    return a;
}
__device__ __forceinline__ void ldmx4(u32& r0, u32& r1, u32& r2, u32& r3, u32 addr) {
    asm volatile("ldmatrix.sync.aligned.m8n8.x4.shared.b16 {%0,%1,%2,%3}, [%4];"
                 : "=r"(r0), "=r"(r1), "=r"(r2), "=r"(r3) : "r"(addr));
}
__device__ __forceinline__ void ldmx4t(u32& r0, u32& r1, u32& r2, u32& r3, u32 addr) {
    asm volatile("ldmatrix.sync.aligned.m8n8.x4.trans.shared.b16 {%0,%1,%2,%3}, [%4];"
                 : "=r"(r0), "=r"(r1), "=r"(r2), "=r"(r3) : "r"(addr));
}
__device__ __forceinline__ void mma_bf16(float (&d)[4],
                                         u32 a0, u32 a1, u32 a2, u32 a3,
                                         u32 b0, u32 b1) {
    asm volatile("mma.sync.aligned.m16n8k16.row.col.f32.bf16.bf16.f32 "
                 "{%0,%1,%2,%3}, {%4,%5,%6,%7}, {%8,%9}, {%0,%1,%2,%3};"
                 : "+f"(d[0]), "+f"(d[1]), "+f"(d[2]), "+f"(d[3])
                 : "r"(a0), "r"(a1), "r"(a2), "r"(a3), "r"(b0), "r"(b1));
}

// 8 floats -> 4 hi bf16x2 regs + 4 lo bf16x2 regs (low half = even index)
__device__ __forceinline__ void cvt8(const float* v, u32* hi, u32* lo) {
    #pragma unroll
    for (int i = 0; i < 4; ++i) {
        u32 u0 = __float_as_uint(v[2 * i])     & 0xffff0000u;
        u32 u1 = __float_as_uint(v[2 * i + 1]) & 0xffff0000u;
        hi[i] = u1 | (u0 >> 16);
        float l0 = v[2 * i]     - __uint_as_float(u0);
        float l1 = v[2 * i + 1] - __uint_as_float(u1);
        asm("cvt.rn.bf16x2.f32 %0, %1, %2;" : "=r"(lo[i]) : "f"(l1), "f"(l0));
    }
}

// ---------------------------------------------------------------------------
// Unified HMMA GEMM kernel.  CTA tile 128 rows x 128 cols, full K resident.
// A planes: bf16 [128][PITCHA bytes], chunk-swizzled (16B chunk ch ^= row&7).
// B planes: bf16 [KPAD][256 bytes], same swizzle over 16 chunks.
// Warps: 2(M) x 4(N); warp tile 64x32; mma m16n8k16, 3 passes (hi/lo).
// MODE 0 (WI):  A = init_messages[b]        (K=165)  out0=v, out1=relu(v)
// MODE 1 (ATT): A = attnei[b2a]-attfea[rev] (K=151)  out0 += v
// MODE 2 (MSG): A = nei[b2a]-msg[b2revb]    (K=128)  out0 = relu(bias + v)
// ---------------------------------------------------------------------------
template<int KPAD, int PITCHA, int MODE>
__global__ void __launch_bounds__(256, 1) k_mma(
    const float* __restrict__ src0, const float* __restrict__ src1,
    const float* __restrict__ W,    const int*   __restrict__ b2a,
    const int*   __restrict__ b2revb, const float* __restrict__ bias,
    float* __restrict__ out0, float* __restrict__ out1)
{
    constexpr int KACT  = (MODE == 0) ? DMSG : (MODE == 1) ? DATT : HH;
    constexpr int NK    = KPAD / 16;      // k16 steps
    constexpr int HC    = KPAD / 2;       // cols per half-row in A fill
    constexpr int NCH   = HC / 8;         // 16B chunks per half-row
    constexpr int ABYTES = 128 * PITCHA;
    constexpr int BPITCH = 256;           // 128 bf16 cols
    constexpr int BBYTES = KPAD * BPITCH;

    extern __shared__ char sm[];
    char* pAhi = sm;
    char* pAlo = sm + ABYTES;
    char* pBhi = sm + 2 * ABYTES;
    char* pBlo = pBhi + BBYTES;
    const u32 uAhi = smem_u32(pAhi);
    const u32 uAlo = smem_u32(pAlo);
    const u32 uBhi = smem_u32(pBhi);
    const u32 uBlo = smem_u32(pBlo);

    const int tid = threadIdx.x;

    // ---- B fill: W[k][n] -> hi/lo planes, swizzled ----
    for (int k = tid; k < KPAD; k += 256) {
        const float* wr = W + (long)k * HH;
        bool kv = k < KACT;
        #pragma unroll 4
        for (int q = 0; q < 16; ++q) {              // 16 chunks of 8 cols
            float v[8];
            if (kv) {
                float4 x0 = ((const float4*)wr)[2 * q];
                float4 x1 = ((const float4*)wr)[2 * q + 1];
                v[0] = x0.x; v[1] = x0.y; v[2] = x0.z; v[3] = x0.w;
                v[4] = x1.x; v[5] = x1.y; v[6] = x1.z; v[7] = x1.w;
            } else {
                #pragma unroll
                for (int t = 0; t < 8; ++t) v[t] = 0.f;
            }
            u32 hi[4], lo[4];
            cvt8(v, hi, lo);
            int sw = (q ^ (k & 7)) * 16;
            *(uint4*)(pBhi + k * BPITCH + sw) = make_uint4(hi[0], hi[1], hi[2], hi[3]);
            *(uint4*)(pBlo + k * BPITCH + sw) = make_uint4(lo[0], lo[1], lo[2], lo[3]);
        }
    }

    // ---- A fill: gather + (subtract) + split, thread = half row ----
    const long row0 = (long)blockIdx.x * 128;
    {
        const int r = tid >> 1, h = tid & 1;
        const long b = row0 + r;
        const bool valid = b < NBb;
        const long bc = valid ? b : 0;

        const float* pA = nullptr;
        const float* pR = nullptr;
        if constexpr (MODE == 0) {
            pA = src0 + bc * DMSG;
        } else if constexpr (MODE == 1) {
            int ia = b2a[bc];
            int ir = b2a[b2revb[bc]];
            pA = src0 + (long)ia * DATT;
            pR = src1 + (long)ir * DATT;
        } else {
            int ia = b2a[bc];
            int ib = b2revb[bc];
            pA = src0 + (long)ia * HH + h * 64;
            pR = src1 + (long)ib * HH + h * 64;
        }

        #pragma unroll
        for (int q = 0; q < NCH; ++q) {
            float v[8];
            if constexpr (MODE == 2) {
                float4 x0 = ((const float4*)pA)[2 * q];
                float4 x1 = ((const float4*)pA)[2 * q + 1];
                float4 y0 = ((const float4*)pR)[2 * q];
                float4 y1 = ((const float4*)pR)[2 * q + 1];
                v[0] = x0.x - y0.x; v[1] = x0.y - y0.y;
                v[2] = x0.z - y0.z; v[3] = x0.w - y0.w;
                v[4] = x1.x - y1.x; v[5] = x1.y - y1.y;
                v[6] = x1.z - y1.z; v[7] = x1.w - y1.w;
            } else {
                #pragma unroll
                for (int t = 0; t < 8; ++t) {
                    int c = h * HC + q * 8 + t;
                    float x = 0.f;
                    if (c < KACT) {
                        if constexpr (MODE == 0) x = pA[c];
                        else                     x = pA[c] - pR[c];
                    }
                    v[t] = x;
                }
            }
            if (!valid) {
                #pragma unroll
                for (int t = 0; t < 8; ++t) v[t] = 0.f;
            }
            u32 hi[4], lo[4];
            cvt8(v, hi, lo);
            int ch = h * NCH + q;
            int sw = (ch ^ (r & 7)) * 16;
            *(uint4*)(pAhi + r * PITCHA + sw) = make_uint4(hi[0], hi[1], hi[2], hi[3]);
            *(uint4*)(pAlo + r * PITCHA + sw) = make_uint4(lo[0], lo[1], lo[2], lo[3]);
        }
    }
    __syncthreads();

    // ---- MMA mainloop ----
    const int lane = tid & 31;
    const int warp = tid >> 5;
    const int wm = warp & 1;      // 0..1 -> rows wm*64
    const int wn = warp >> 1;     // 0..3 -> cols wn*32

    float acc[4][4][4];
    #pragma unroll
    for (int mt = 0; mt < 4; ++mt)
        #pragma unroll
        for (int nt = 0; nt < 4; ++nt)
            #pragma unroll
            for (int e = 0; e < 4; ++e) acc[mt][nt][e] = 0.f;

    // A ldmatrix lane geometry (per mt): row + chunk-parity
    const int aj   = lane >> 3;             // tile 0..3
    const int ai   = lane & 7;              // row in tile
    const int ajk  = aj >> 1;               // chunk offset 0/1
    const int ajr  = (aj & 1) * 8;          // row offset 0/8
    // B ldmatrix lane geometry
    const int bkl  = lane & 15;             // k-row offset
    const int bchl = lane >> 4;             // n-chunk offset 0/1

    for (int ks = 0; ks < NK; ++ks) {
        u32 ah[4][4], al[4][4];
        #pragma unroll
        for (int mt = 0; mt < 4; ++mt) {
            int arow = wm * 64 + mt * 16 + ajr + ai;
            int ch   = 2 * ks + ajk;
            u32 off  = (u32)(arow * PITCHA) + (u32)((ch ^ (arow & 7)) << 4);
            ldmx4(ah[mt][0], ah[mt][1], ah[mt][2], ah[mt][3], uAhi + off);
            ldmx4(al[mt][0], al[mt][1], al[mt][2], al[mt][3], uAlo + off);
        }
        u32 bh[4][2], bl[4][2];
        #pragma unroll
        for (int nt2 = 0; nt2 < 2; ++nt2) {
            int krow = ks * 16 + bkl;
            int ch   = wn * 4 + nt2 * 2 + bchl;
            u32 off  = (u32)(krow * BPITCH) + (u32)((ch ^ (krow & 7)) << 4);
            u32 r0, r1, r2, r3;
            ldmx4t(r0, r1, r2, r3, uBhi + off);
            bh[2 * nt2][0] = r0; bh[2 * nt2][1] = r1;
            bh[2 * nt2 + 1][0] = r2; bh[2 * nt2 + 1][1] = r3;
            ldmx4t(r0, r1, r2, r3, uBlo + off);
            bl[2 * nt2][0] = r0; bl[2 * nt2][1] = r1;
            bl[2 * nt2 + 1][0] = r2; bl[2 * nt2 + 1][1] = r3;
        }
        #pragma unroll
        for (int mt = 0; mt < 4; ++mt)
            #pragma unroll
            for (int nt = 0; nt < 4; ++nt) {
                mma_bf16(acc[mt][nt], ah[mt][0], ah[mt][1], ah[mt][2], ah[mt][3],
                         bh[nt][0], bh[nt][1]);
                mma_bf16(acc[mt][nt], ah[mt][0], ah[mt][1], ah[mt][2], ah[mt][3],
                         bl[nt][0], bl[nt][1]);
                mma_bf16(acc[mt][nt], al[mt][0], al[mt][1], al[mt][2], al[mt][3],
                         bh[nt][0], bh[nt][1]);
            }
    }

    // ---- Epilogue: fragment layout c0,c1 -> row gr; c2,c3 -> row gr+8 ----
    const int gr = lane >> 2;
    const int gc = (lane & 3) * 2;
    #pragma unroll
    for (int mt = 0; mt < 4; ++mt) {
        #pragma unroll
        for (int nt = 0; nt < 4; ++nt) {
            long r1 = row0 + wm * 64 + mt * 16 + gr;
            long r2 = r1 + 8;
            int  c  = wn * 32 + nt * 8 + gc;
            const float* a = acc[mt][nt];
            if (r1 < NBb) {
                size_t o = (size_t)r1 * HH + c;
                if constexpr (MODE == 0) {
                    *(float2*)(out0 + o) = make_float2(a[0], a[1]);
                    *(float2*)(out1 + o) = make_float2(fmaxf(a[0], 0.f), fmaxf(a[1], 0.f));
                } else if constexpr (MODE == 1) {
                    float2 b = *(const float2*)(out0 + o);
                    *(float2*)(out0 + o) = make_float2(b.x + a[0], b.y + a[1]);
                } else {
                    float2 b = *(const float2*)(bias + o);
                    *(float2*)(out0 + o) = make_float2(fmaxf(b.x + a[0], 0.f),
                                                       fmaxf(b.y + a[1], 0.f));
                }
            }
            if (r2 < NBb) {
                size_t o = (size_t)r2 * HH + c;
                if constexpr (MODE == 0) {
                    *(float2*)(out0 + o) = make_float2(a[2], a[3]);
                    *(float2*)(out1 + o) = make_float2(fmaxf(a[2], 0.f), fmaxf(a[3], 0.f));
                } else if constexpr (MODE == 1) {
                    float2 b = *(const float2*)(out0 + o);
                    *(float2*)(out0 + o) = make_float2(b.x + a[2], b.y + a[3]);
                } else {
                    float2 b = *(const float2*)(bias + o);
                    *(float2*)(out0 + o) = make_float2(fmaxf(b.x + a[2], 0.f),
                                                       fmaxf(b.y + a[3], 0.f));
                }
            }
        }
    }
}

// ---------------------------------------------------------------------------
// Aggregation kernels (DRAM-bound)
// ---------------------------------------------------------------------------
__global__ void __launch_bounds__(256) k_att_agg(
    const float* __restrict__ attfea, const int* __restrict__ a2att,
    float* __restrict__ attnei)
{
    const int warp = threadIdx.x >> 5, lane = threadIdx.x & 31;
    const int a = blockIdx.x * 8 + warp;
    if (a >= NAa) return;
    int idx[6];
    #pragma unroll
    for (int j = 0; j < 6; ++j) idx[j] = a2att[a * 6 + j];
    float acc[5] = {0.f, 0.f, 0.f, 0.f, 0.f};
    #pragma unroll
    for (int j = 0; j < 6; ++j) {
        const float* p = attfea + (long)idx[j] * DATT;
        #pragma unroll
        for (int t = 0; t < 5; ++t) {
            int c = t * 32 + lane;
            if (c < DATT) acc[t] += p[c];
        }
    }
    float* o = attnei + (long)a * DATT;
    #pragma unroll
    for (int t = 0; t < 5; ++t) {
        int c = t * 32 + lane;
        if (c < DATT) o[c] = acc[t];
    }
}

__global__ void __launch_bounds__(256) k_nei_agg(
    const float* __restrict__ msg, const int* __restrict__ a2nei,
    float* __restrict__ nei)
{
    const int warp = threadIdx.x >> 5, lane = threadIdx.x & 31;
    const int a = blockIdx.x * 8 + warp;
    if (a >= NAa) return;
    int idx[6];
    #pragma unroll
    for (int j = 0; j < 6; ++j) idx[j] = a2nei[a * 6 + j];
    float4 acc = make_float4(0.f, 0.f, 0.f, 0.f);
    #pragma unroll
    for (int j = 0; j < 6; ++j) {
        float4 v = *(const float4*)(msg + (long)idx[j] * HH + lane * 4);
        acc.x += v.x; acc.y += v.y; acc.z += v.z; acc.w += v.w;
    }
    *(float4*)(nei + (long)a * HH + lane * 4) = acc;
}

// Dummy: shifts launch index so ncu (-s 5 -c 1) profiles the msg GEMM (#6).
__global__ void k_dummy(float* p) { if (threadIdx.x == 0) p[0] = 0.f; }

// ---------------------------------------------------------------------------
extern "C" void kernel_launch(void* const* d_in, const int* in_sizes, int n_in,
                              void* d_out, int out_size) {
    (void)in_sizes; (void)n_in; (void)out_size;

    const float* init_messages = (const float*)d_in[0];
    const float* attfea        = (const float*)d_in[1];
    const float* W_i           = (const float*)d_in[2];
    const float* W_h           = (const float*)d_in[3];  // [279][128]
    const int*   a2nei         = (const int*)d_in[4];
    const int*   a2att         = (const int*)d_in[5];
    const int*   b2a           = (const int*)d_in[6];
    const int*   b2revb        = (const int*)d_in[7];
    float*       out           = (float*)d_out;

    // KPAD / PITCHA (bytes): wi 176/384, att 160/384, msg 128/256
    constexpr int SM_WI  = 2 * (128 * 384) + 2 * (176 * 256);   // 188416
    constexpr int SM_ATT = 2 * (128 * 384) + 2 * (160 * 256);   // 180224
    constexpr int SM_MSG = 2 * (128 * 256) + 2 * (128 * 256);   // 131072

    cudaFuncSetAttribute((const void*)k_mma<176, 384, 0>,
                         cudaFuncAttributeMaxDynamicSharedMemorySize, SM_WI);
    cudaFuncSetAttribute((const void*)k_mma<160, 384, 1>,
                         cudaFuncAttributeMaxDynamicSharedMemorySize, SM_ATT);
    cudaFuncSetAttribute((const void*)k_mma<128, 256, 2>,
                         cudaFuncAttributeMaxDynamicSharedMemorySize, SM_MSG);

    float *bias, *m0, *m1, *nei, *attnei;
    cudaGetSymbolAddress((void**)&bias,   g_bias2);
    cudaGetSymbolAddress((void**)&m0,     g_msg0);
    cudaGetSymbolAddress((void**)&m1,     g_msg1);
    cudaGetSymbolAddress((void**)&nei,    g_nei);
    cudaGetSymbolAddress((void**)&attnei, g_attnei);

    const int gb = (NBb + 127) / 128;   // 3907
    const int ga = NAa / 8;             // 31250

    k_dummy<<<1, 32>>>(nei);                                     // launch 1

    k_att_agg<<<ga, 256>>>(attfea, a2att, attnei);               // 2
    k_mma<176, 384, 0><<<gb, 256, SM_WI>>>(                      // 3 (WI)
        init_messages, nullptr, W_i, nullptr, nullptr, nullptr, bias, m0);
    k_mma<160, 384, 1><<<gb, 256, SM_ATT>>>(                     // 4 (ATT)
        attnei, attfea, W_h + HH * HH, b2a, b2revb, nullptr, bias, nullptr);

    float* cur = m0;
    float* nxt = m1;
    for (int it = 0; it < 5; ++it) {
        k_nei_agg<<<ga, 256>>>(cur, a2nei, nei);                 // 5, 7, ...
        float* o = (it == 4) ? out : nxt;
        k_mma<128, 256, 2><<<gb, 256, SM_MSG>>>(                 // 6 <- profiled
            nei, cur, W_h, b2a, b2revb, bias, o, nullptr);
        float* t = cur; cur = nxt; nxt = t;
    }
}

// round 10
// speedup vs baseline: 2.6321x; 1.2614x over previous
#include <cuda_runtime.h>
#include <cstdint>

// ---------------------------------------------------------------------------
// MPNEncoder, DEPTH=6, H=128 — bf16 hi/lo split GEMMs on the legacy HMMA path
// (mma.sync.m16n8k16.bf16; tcgen05 is PTX-gated off under compute_103).
//
//   inp        = init_messages @ W_i                       (once)   [MODE 0]
//   attnei[a]  = sum_j attfea[a2attached[a,j]]             (once)
//   bias2[b]   = inp[b] + (attnei[b2a] - attfea[b2a_rev]) @ W_h[128:]  [MODE 1]
//   msg        = relu(inp)
//   5x: nei[a] = sum_j msg[a2nei[a,j]]
//       msg    = relu(bias2 + (nei[b2a] - msg[b2revb]) @ W_h[:128])    [MODE 2]
//
// Split: v = hi (fp32 with low 16 mantissa bits zeroed) + lo (bf16 residual).
// D = Ahi*Bhi + Ahi*Blo + Alo*Bhi, fp32 accum.
// R9: 512 threads/CTA (4 warps/SMSP), warp grid 4Mx4N, warp tile 32x32.
// ---------------------------------------------------------------------------

constexpr int NBb  = 500000;
constexpr int NAa  = 250000;
constexpr int DMSG = 165;
constexpr int DATT = 151;
constexpr int HH   = 128;

__device__ float g_bias2 [(size_t)NBb * HH];
__device__ float g_msg0  [(size_t)NBb * HH];
__device__ float g_msg1  [(size_t)NBb * HH];
__device__ float g_nei   [(size_t)NAa * HH];
__device__ float g_attnei[(size_t)NAa * DATT];

typedef unsigned int u32;

__device__ __forceinline__ u32 smem_u32(const void* p) {
    u32 a;
    asm("{ .reg .u64 t; cvta.to.shared.u64 t, %1; cvt.u32.u64 %0, t; }"
        : "=r"(a) : "l"(p));
    return a;
}
__device__ __forceinline__ void ldmx4(u32& r0, u32& r1, u32& r2, u32& r3, u32 addr) {
    asm volatile("ldmatrix.sync.aligned.m8n8.x4.shared.b16 {%0,%1,%2,%3}, [%4];"
                 : "=r"(r0), "=r"(r1), "=r"(r2), "=r"(r3) : "r"(addr));
}
__device__ __forceinline__ void ldmx4t(u32& r0, u32& r1, u32& r2, u32& r3, u32 addr) {
    asm volatile("ldmatrix.sync.aligned.m8n8.x4.trans.shared.b16 {%0,%1,%2,%3}, [%4];"
                 : "=r"(r0), "=r"(r1), "=r"(r2), "=r"(r3) : "r"(addr));
}
__device__ __forceinline__ void mma_bf16(float (&d)[4],
                                         u32 a0, u32 a1, u32 a2, u32 a3,
                                         u32 b0, u32 b1) {
    asm volatile("mma.sync.aligned.m16n8k16.row.col.f32.bf16.bf16.f32 "
                 "{%0,%1,%2,%3}, {%4,%5,%6,%7}, {%8,%9}, {%0,%1,%2,%3};"
                 : "+f"(d[0]), "+f"(d[1]), "+f"(d[2]), "+f"(d[3])
                 : "r"(a0), "r"(a1), "r"(a2), "r"(a3), "r"(b0), "r"(b1));
}

// 8 floats -> 4 hi bf16x2 regs + 4 lo bf16x2 regs (low half = even index)
__device__ __forceinline__ void cvt8(const float* v, u32* hi, u32* lo) {
    #pragma unroll
    for (int i = 0; i < 4; ++i) {
        u32 u0 = __float_as_uint(v[2 * i])     & 0xffff0000u;
        u32 u1 = __float_as_uint(v[2 * i + 1]) & 0xffff0000u;
        hi[i] = u1 | (u0 >> 16);
        float l0 = v[2 * i]     - __uint_as_float(u0);
        float l1 = v[2 * i + 1] - __uint_as_float(u1);
        asm("cvt.rn.bf16x2.f32 %0, %1, %2;" : "=r"(lo[i]) : "f"(l1), "f"(l0));
    }
}

// ---------------------------------------------------------------------------
// Unified HMMA GEMM kernel.  CTA tile 128 rows x 128 cols, full K resident.
// A planes: bf16 [128][PITCHA bytes], chunk-swizzled (16B chunk ch ^= row&7).
// B planes: bf16 [KPAD][256 bytes], same swizzle over 16 chunks.
// 512 threads: warps 4(M) x 4(N); warp tile 32x32; 3 mma passes (hi/lo).
// MODE 0 (WI):  A = init_messages[b]        (K=165)  out0=v, out1=relu(v)
// MODE 1 (ATT): A = attnei[b2a]-attfea[rev] (K=151)  out0 += v
// MODE 2 (MSG): A = nei[b2a]-msg[b2revb]    (K=128)  out0 = relu(bias + v)
// ---------------------------------------------------------------------------
template<int KPAD, int PITCHA, int MODE>
__global__ void __launch_bounds__(512, 1) k_mma(
    const float* __restrict__ src0, const float* __restrict__ src1,
    const float* __restrict__ W,    const int*   __restrict__ b2a,
    const int*   __restrict__ b2revb, const float* __restrict__ bias,
    float* __restrict__ out0, float* __restrict__ out1)
{
    constexpr int KACT  = (MODE == 0) ? DMSG : (MODE == 1) ? DATT : HH;
    constexpr int NK    = KPAD / 16;      // k16 steps
    constexpr int NCH   = KPAD / 8;       // 16B chunks per A row
    constexpr int ABYTES = 128 * PITCHA;
    constexpr int BPITCH = 256;           // 128 bf16 cols
    constexpr int BBYTES = KPAD * BPITCH;

    extern __shared__ char sm[];
    char* pAhi = sm;
    char* pAlo = sm + ABYTES;
    char* pBhi = sm + 2 * ABYTES;
    char* pBlo = pBhi + BBYTES;
    const u32 uAhi = smem_u32(pAhi);
    const u32 uAlo = smem_u32(pAlo);
    const u32 uBhi = smem_u32(pBhi);
    const u32 uBlo = smem_u32(pBlo);

    const int tid = threadIdx.x;

    // ---- B fill: W[k][n] -> hi/lo planes, swizzled ----
    for (int k = tid; k < KPAD; k += 512) {
        const float* wr = W + (long)k * HH;
        bool kv = k < KACT;
        #pragma unroll 4
        for (int q = 0; q < 16; ++q) {              // 16 chunks of 8 cols
            float v[8];
            if (kv) {
                float4 x0 = ((const float4*)wr)[2 * q];
                float4 x1 = ((const float4*)wr)[2 * q + 1];
                v[0] = x0.x; v[1] = x0.y; v[2] = x0.z; v[3] = x0.w;
                v[4] = x1.x; v[5] = x1.y; v[6] = x1.z; v[7] = x1.w;
            } else {
                #pragma unroll
                for (int t = 0; t < 8; ++t) v[t] = 0.f;
            }
            u32 hi[4], lo[4];
            cvt8(v, hi, lo);
            int sw = (q ^ (k & 7)) * 16;
            *(uint4*)(pBhi + k * BPITCH + sw) = make_uint4(hi[0], hi[1], hi[2], hi[3]);
            *(uint4*)(pBlo + k * BPITCH + sw) = make_uint4(lo[0], lo[1], lo[2], lo[3]);
        }
    }

    // ---- A fill: gather + (subtract) + split; thread = quarter row,
    //      chunk-interleaved (q = h, h+4, ...) so any NCH works ----
    const long row0 = (long)blockIdx.x * 128;
    {
        const int r = tid >> 2, h = tid & 3;
        const long b = row0 + r;
        const bool valid = b < NBb;
        const long bc = valid ? b : 0;

        const float* pA = nullptr;
        const float* pR = nullptr;
        if constexpr (MODE == 0) {
            pA = src0 + bc * DMSG;
        } else if constexpr (MODE == 1) {
            int ia = b2a[bc];
            int ir = b2a[b2revb[bc]];
            pA = src0 + (long)ia * DATT;
            pR = src1 + (long)ir * DATT;
        } else {
            int ia = b2a[bc];
            int ib = b2revb[bc];
            pA = src0 + (long)ia * HH;
            pR = src1 + (long)ib * HH;
        }

        #pragma unroll
        for (int q = h; q < NCH; q += 4) {
            float v[8];
            if constexpr (MODE == 2) {
                float4 x0 = ((const float4*)pA)[2 * q];
                float4 x1 = ((const float4*)pA)[2 * q + 1];
                float4 y0 = ((const float4*)pR)[2 * q];
                float4 y1 = ((const float4*)pR)[2 * q + 1];
                v[0] = x0.x - y0.x; v[1] = x0.y - y0.y;
                v[2] = x0.z - y0.z; v[3] = x0.w - y0.w;
                v[4] = x1.x - y1.x; v[5] = x1.y - y1.y;
                v[6] = x1.z - y1.z; v[7] = x1.w - y1.w;
            } else {
                #pragma unroll
                for (int t = 0; t < 8; ++t) {
                    int c = q * 8 + t;
                    float x = 0.f;
                    if (c < KACT) {
                        if constexpr (MODE == 0) x = pA[c];
                        else                     x = pA[c] - pR[c];
                    }
                    v[t] = x;
                }
            }
            if (!valid) {
                #pragma unroll
                for (int t = 0; t < 8; ++t) v[t] = 0.f;
            }
            u32 hi[4], lo[4];
            cvt8(v, hi, lo);
            int sw = (q ^ (r & 7)) * 16;
            *(uint4*)(pAhi + r * PITCHA + sw) = make_uint4(hi[0], hi[1], hi[2], hi[3]);
            *(uint4*)(pAlo + r * PITCHA + sw) = make_uint4(lo[0], lo[1], lo[2], lo[3]);
        }
    }
    __syncthreads();

    // ---- MMA mainloop: warp (wm 0..3 rows, wn 0..3 cols), tile 32x32 ----
    const int lane = tid & 31;
    const int warp = tid >> 5;
    const int wm = warp & 3;      // rows wm*32
    const int wn = warp >> 2;     // cols wn*32

    float acc[2][4][4];
    #pragma unroll
    for (int mt = 0; mt < 2; ++mt)
        #pragma unroll
        for (int nt = 0; nt < 4; ++nt)
            #pragma unroll
            for (int e = 0; e < 4; ++e) acc[mt][nt][e] = 0.f;

    // A ldmatrix lane geometry (per mt): row + chunk-parity
    const int aj   = lane >> 3;             // tile 0..3
    const int ai   = lane & 7;              // row in tile
    const int ajk  = aj >> 1;               // chunk offset 0/1
    const int ajr  = (aj & 1) * 8;          // row offset 0/8
    // B ldmatrix lane geometry
    const int bkl  = lane & 15;             // k-row offset
    const int bchl = lane >> 4;             // n-chunk offset 0/1

    #pragma unroll 2
    for (int ks = 0; ks < NK; ++ks) {
        u32 ah[2][4], al[2][4];
        #pragma unroll
        for (int mt = 0; mt < 2; ++mt) {
            int arow = wm * 32 + mt * 16 + ajr + ai;
            int ch   = 2 * ks + ajk;
            u32 off  = (u32)(arow * PITCHA) + (u32)((ch ^ (arow & 7)) << 4);
            ldmx4(ah[mt][0], ah[mt][1], ah[mt][2], ah[mt][3], uAhi + off);
            ldmx4(al[mt][0], al[mt][1], al[mt][2], al[mt][3], uAlo + off);
        }
        u32 bh[4][2], bl[4][2];
        #pragma unroll
        for (int nt2 = 0; nt2 < 2; ++nt2) {
            int krow = ks * 16 + bkl;
            int ch   = wn * 4 + nt2 * 2 + bchl;
            u32 off  = (u32)(krow * BPITCH) + (u32)((ch ^ (krow & 7)) << 4);
            u32 r0, r1, r2, r3;
            ldmx4t(r0, r1, r2, r3, uBhi + off);
            bh[2 * nt2][0] = r0; bh[2 * nt2][1] = r1;
            bh[2 * nt2 + 1][0] = r2; bh[2 * nt2 + 1][1] = r3;
            ldmx4t(r0, r1, r2, r3, uBlo + off);
            bl[2 * nt2][0] = r0; bl[2 * nt2][1] = r1;
            bl[2 * nt2 + 1][0] = r2; bl[2 * nt2 + 1][1] = r3;
        }
        #pragma unroll
        for (int mt = 0; mt < 2; ++mt)
            #pragma unroll
            for (int nt = 0; nt < 4; ++nt) {
                mma_bf16(acc[mt][nt], ah[mt][0], ah[mt][1], ah[mt][2], ah[mt][3],
                         bh[nt][0], bh[nt][1]);
                mma_bf16(acc[mt][nt], ah[mt][0], ah[mt][1], ah[mt][2], ah[mt][3],
                         bl[nt][0], bl[nt][1]);
                mma_bf16(acc[mt][nt], al[mt][0], al[mt][1], al[mt][2], al[mt][3],
                         bh[nt][0], bh[nt][1]);
            }
    }

    // ---- Epilogue: fragment c0,c1 -> row gr; c2,c3 -> row gr+8 ----
    const int gr = lane >> 2;
    const int gc = (lane & 3) * 2;
    #pragma unroll
    for (int mt = 0; mt < 2; ++mt) {
        #pragma unroll
        for (int nt = 0; nt < 4; ++nt) {
            long r1 = row0 + wm * 32 + mt * 16 + gr;
            long r2 = r1 + 8;
            int  c  = wn * 32 + nt * 8 + gc;
            const float* a = acc[mt][nt];
            if (r1 < NBb) {
                size_t o = (size_t)r1 * HH + c;
                if constexpr (MODE == 0) {
                    *(float2*)(out0 + o) = make_float2(a[0], a[1]);
                    *(float2*)(out1 + o) = make_float2(fmaxf(a[0], 0.f), fmaxf(a[1], 0.f));
                } else if constexpr (MODE == 1) {
                    float2 b = *(const float2*)(out0 + o);
                    *(float2*)(out0 + o) = make_float2(b.x + a[0], b.y + a[1]);
                } else {
                    float2 b = *(const float2*)(bias + o);
                    *(float2*)(out0 + o) = make_float2(fmaxf(b.x + a[0], 0.f),
                                                       fmaxf(b.y + a[1], 0.f));
                }
            }
            if (r2 < NBb) {
                size_t o = (size_t)r2 * HH + c;
                if constexpr (MODE == 0) {
                    *(float2*)(out0 + o) = make_float2(a[2], a[3]);
                    *(float2*)(out1 + o) = make_float2(fmaxf(a[2], 0.f), fmaxf(a[3], 0.f));
                } else if constexpr (MODE == 1) {
                    float2 b = *(const float2*)(out0 + o);
                    *(float2*)(out0 + o) = make_float2(b.x + a[2], b.y + a[3]);
                } else {
                    float2 b = *(const float2*)(bias + o);
                    *(float2*)(out0 + o) = make_float2(fmaxf(b.x + a[2], 0.f),
                                                       fmaxf(b.y + a[3], 0.f));
                }
            }
        }
    }
}

// ---------------------------------------------------------------------------
// Aggregation kernels (DRAM-bound)
// ---------------------------------------------------------------------------
__global__ void __launch_bounds__(256) k_att_agg(
    const float* __restrict__ attfea, const int* __restrict__ a2att,
    float* __restrict__ attnei)
{
    const int warp = threadIdx.x >> 5, lane = threadIdx.x & 31;
    const int a = blockIdx.x * 8 + warp;
    if (a >= NAa) return;
    int idx[6];
    #pragma unroll
    for (int j = 0; j < 6; ++j) idx[j] = a2att[a * 6 + j];
    float acc[5] = {0.f, 0.f, 0.f, 0.f, 0.f};
    #pragma unroll
    for (int j = 0; j < 6; ++j) {
        const float* p = attfea + (long)idx[j] * DATT;
        #pragma unroll
        for (int t = 0; t < 5; ++t) {
            int c = t * 32 + lane;
            if (c < DATT) acc[t] += p[c];
        }
    }
    float* o = attnei + (long)a * DATT;
    #pragma unroll
    for (int t = 0; t < 5; ++t) {
        int c = t * 32 + lane;
        if (c < DATT) o[c] = acc[t];
    }
}

__global__ void __launch_bounds__(256) k_nei_agg(
    const float* __restrict__ msg, const int* __restrict__ a2nei,
    float* __restrict__ nei)
{
    const int warp = threadIdx.x >> 5, lane = threadIdx.x & 31;
    const int a = blockIdx.x * 8 + warp;
    if (a >= NAa) return;
    int idx[6];
    #pragma unroll
    for (int j = 0; j < 6; ++j) idx[j] = a2nei[a * 6 + j];
    float4 acc = make_float4(0.f, 0.f, 0.f, 0.f);
    #pragma unroll
    for (int j = 0; j < 6; ++j) {
        float4 v = *(const float4*)(msg + (long)idx[j] * HH + lane * 4);
        acc.x += v.x; acc.y += v.y; acc.z += v.z; acc.w += v.w;
    }
    *(float4*)(nei + (long)a * HH + lane * 4) = acc;
}

// Dummy: shifts launch index so ncu (-s 5 -c 1) profiles the msg GEMM (#6).
__global__ void k_dummy(float* p) { if (threadIdx.x == 0) p[0] = 0.f; }

// ---------------------------------------------------------------------------
extern "C" void kernel_launch(void* const* d_in, const int* in_sizes, int n_in,
                              void* d_out, int out_size) {
    (void)in_sizes; (void)n_in; (void)out_size;

    const float* init_messages = (const float*)d_in[0];
    const float* attfea        = (const float*)d_in[1];
    const float* W_i           = (const float*)d_in[2];
    const float* W_h           = (const float*)d_in[3];  // [279][128]
    const int*   a2nei         = (const int*)d_in[4];
    const int*   a2att         = (const int*)d_in[5];
    const int*   b2a           = (const int*)d_in[6];
    const int*   b2revb        = (const int*)d_in[7];
    float*       out           = (float*)d_out;

    // KPAD / PITCHA (bytes): wi 176/384, att 160/384, msg 128/256
    constexpr int SM_WI  = 2 * (128 * 384) + 2 * (176 * 256);   // 188416
    constexpr int SM_ATT = 2 * (128 * 384) + 2 * (160 * 256);   // 180224
    constexpr int SM_MSG = 2 * (128 * 256) + 2 * (128 * 256);   // 131072

    cudaFuncSetAttribute((const void*)k_mma<176, 384, 0>,
                         cudaFuncAttributeMaxDynamicSharedMemorySize, SM_WI);
    cudaFuncSetAttribute((const void*)k_mma<160, 384, 1>,
                         cudaFuncAttributeMaxDynamicSharedMemorySize, SM_ATT);
    cudaFuncSetAttribute((const void*)k_mma<128, 256, 2>,
                         cudaFuncAttributeMaxDynamicSharedMemorySize, SM_MSG);

    float *bias, *m0, *m1, *nei, *attnei;
    cudaGetSymbolAddress((void**)&bias,   g_bias2);
    cudaGetSymbolAddress((void**)&m0,     g_msg0);
    cudaGetSymbolAddress((void**)&m1,     g_msg1);
    cudaGetSymbolAddress((void**)&nei,    g_nei);
    cudaGetSymbolAddress((void**)&attnei, g_attnei);

    const int gb = (NBb + 127) / 128;   // 3907
    const int ga = NAa / 8;             // 31250

    k_dummy<<<1, 32>>>(nei);                                     // launch 1

    k_att_agg<<<ga, 256>>>(attfea, a2att, attnei);               // 2
    k_mma<176, 384, 0><<<gb, 512, SM_WI>>>(                      // 3 (WI)
        init_messages, nullptr, W_i, nullptr, nullptr, nullptr, bias, m0);
    k_mma<160, 384, 1><<<gb, 512, SM_ATT>>>(                     // 4 (ATT)
        attnei, attfea, W_h + HH * HH, b2a, b2revb, nullptr, bias, nullptr);

    float* cur = m0;
    float* nxt = m1;
    for (int it = 0; it < 5; ++it) {
        k_nei_agg<<<ga, 256>>>(cur, a2nei, nei);                 // 5, 7, ...
        float* o = (it == 4) ? out : nxt;
        k_mma<128, 256, 2><<<gb, 512, SM_MSG>>>(                 // 6 <- profiled
            nei, cur, W_h, b2a, b2revb, bias, o, nullptr);
        float* t = cur; cur = nxt; nxt = t;
    }
}

// round 11
// speedup vs baseline: 2.6601x; 1.0106x over previous
#include <cuda_runtime.h>
#include <cstdint>

// ---------------------------------------------------------------------------
// MPNEncoder, DEPTH=6, H=128 — bf16 hi/lo split GEMMs on legacy HMMA
// (mma.sync.m16n8k16.bf16; tcgen05 is PTX-gated off under compute_103).
//
//   attnei[a]  = sum_j attfea[a2attached[a,j]]             (once)
//   FUSED bias kernel (two accumulation phases, same registers):
//     acc  = init_messages @ W_i  +  (attnei[b2a]-attfea[b2a_rev]) @ W_h[128:]
//     bias = acc ; msg0 = relu(acc ... wait: msg0 = relu(inp) only)
//   NOTE: msg0 must be relu(inp) (inp = phase-0 partial), so phase-0 result is
//   written to msg0 before phase 1 continues accumulating.   <-- handled below
//   5x: nei[a] = sum_j msg[a2nei[a,j]]
//       msg    = relu(bias + (nei[b2a] - msg[b2revb]) @ W_h[:128])
//
// Split: v = hi (fp32, low 16 mantissa bits zeroed) + lo (bf16 of residual).
// D = Ahi*Bhi + Ahi*Blo + Alo*Bhi, fp32 accum.
// ---------------------------------------------------------------------------

constexpr int NBb  = 500000;
constexpr int NAa  = 250000;
constexpr int DMSG = 165;
constexpr int DATT = 151;
constexpr int HH   = 128;

__device__ float g_bias2 [(size_t)NBb * HH];
__device__ float g_msg0  [(size_t)NBb * HH];
__device__ float g_msg1  [(size_t)NBb * HH];
__device__ float g_nei   [(size_t)NAa * HH];
__device__ float g_attnei[(size_t)NAa * DATT];

typedef unsigned int u32;

__device__ __forceinline__ u32 smem_u32(const void* p) {
    u32 a;
    asm("{ .reg .u64 t; cvta.to.shared.u64 t, %1; cvt.u32.u64 %0, t; }"
        : "=r"(a) : "l"(p));
    return a;
}
__device__ __forceinline__ void ldmx4(u32& r0, u32& r1, u32& r2, u32& r3, u32 addr) {
    asm volatile("ldmatrix.sync.aligned.m8n8.x4.shared.b16 {%0,%1,%2,%3}, [%4];"
                 : "=r"(r0), "=r"(r1), "=r"(r2), "=r"(r3) : "r"(addr));
}
__device__ __forceinline__ void ldmx4t(u32& r0, u32& r1, u32& r2, u32& r3, u32 addr) {
    asm volatile("ldmatrix.sync.aligned.m8n8.x4.trans.shared.b16 {%0,%1,%2,%3}, [%4];"
                 : "=r"(r0), "=r"(r1), "=r"(r2), "=r"(r3) : "r"(addr));
}
__device__ __forceinline__ void mma_bf16(float (&d)[4],
                                         u32 a0, u32 a1, u32 a2, u32 a3,
                                         u32 b0, u32 b1) {
    asm volatile("mma.sync.aligned.m16n8k16.row.col.f32.bf16.bf16.f32 "
                 "{%0,%1,%2,%3}, {%4,%5,%6,%7}, {%8,%9}, {%0,%1,%2,%3};"
                 : "+f"(d[0]), "+f"(d[1]), "+f"(d[2]), "+f"(d[3])
                 : "r"(a0), "r"(a1), "r"(a2), "r"(a3), "r"(b0), "r"(b1));
}

// 8 floats -> 4 hi bf16x2 regs + 4 lo bf16x2 regs (low half = even index)
__device__ __forceinline__ void cvt8(const float* v, u32* hi, u32* lo) {
    #pragma unroll
    for (int i = 0; i < 4; ++i) {
        u32 u0 = __float_as_uint(v[2 * i])     & 0xffff0000u;
        u32 u1 = __float_as_uint(v[2 * i + 1]) & 0xffff0000u;
        hi[i] = u1 | (u0 >> 16);
        float l0 = v[2 * i]     - __uint_as_float(u0);
        float l1 = v[2 * i + 1] - __uint_as_float(u1);
        asm("cvt.rn.bf16x2.f32 %0, %1, %2;" : "=r"(lo[i]) : "f"(l1), "f"(l0));
    }
}

// B fill: W[k][n] (n=128) -> swizzled hi/lo bf16 planes, pitch 256B.
__device__ __forceinline__ void fill_B(const float* __restrict__ W,
                                       int KPADr, int KACTr,
                                       char* pBhi, char* pBlo, int tid, int NT) {
    for (int k = tid; k < KPADr; k += NT) {
        const float* wr = W + (long)k * HH;
        bool kv = k < KACTr;
        #pragma unroll 4
        for (int q = 0; q < 16; ++q) {
            float v[8];
            if (kv) {
                float4 x0 = ((const float4*)wr)[2 * q];
                float4 x1 = ((const float4*)wr)[2 * q + 1];
                v[0] = x0.x; v[1] = x0.y; v[2] = x0.z; v[3] = x0.w;
                v[4] = x1.x; v[5] = x1.y; v[6] = x1.z; v[7] = x1.w;
            } else {
                #pragma unroll
                for (int t = 0; t < 8; ++t) v[t] = 0.f;
            }
            u32 hi[4], lo[4];
            cvt8(v, hi, lo);
            int sw = (q ^ (k & 7)) * 16;
            *(uint4*)(pBhi + k * 256 + sw) = make_uint4(hi[0], hi[1], hi[2], hi[3]);
            *(uint4*)(pBlo + k * 256 + sw) = make_uint4(lo[0], lo[1], lo[2], lo[3]);
        }
    }
}

// Shared MMA mainloop (warp tile 32x32, mt=2, nt=4). NK runtime.
template<int PITCHA>
__device__ __forceinline__ void mma_loop(
    int NK, u32 uAhi, u32 uAlo, u32 uBhi, u32 uBlo,
    float (&acc)[2][4][4], int lane, int wm, int wn)
{
    const int aj   = lane >> 3;
    const int ai   = lane & 7;
    const int ajk  = aj >> 1;
    const int ajr  = (aj & 1) * 8;
    const int bkl  = lane & 15;
    const int bchl = lane >> 4;

    #pragma unroll 2
    for (int ks = 0; ks < NK; ++ks) {
        u32 ah[2][4], al[2][4];
        #pragma unroll
        for (int mt = 0; mt < 2; ++mt) {
            int arow = wm * 32 + mt * 16 + ajr + ai;
            int ch   = 2 * ks + ajk;
            u32 off  = (u32)(arow * PITCHA) + (u32)((ch ^ (arow & 7)) << 4);
            ldmx4(ah[mt][0], ah[mt][1], ah[mt][2], ah[mt][3], uAhi + off);
            ldmx4(al[mt][0], al[mt][1], al[mt][2], al[mt][3], uAlo + off);
        }
        u32 bh[4][2], bl[4][2];
        #pragma unroll
        for (int nt2 = 0; nt2 < 2; ++nt2) {
            int krow = ks * 16 + bkl;
            int ch   = wn * 4 + nt2 * 2 + bchl;
            u32 off  = (u32)(krow * 256) + (u32)((ch ^ (krow & 7)) << 4);
            u32 r0, r1, r2, r3;
            ldmx4t(r0, r1, r2, r3, uBhi + off);
            bh[2 * nt2][0] = r0; bh[2 * nt2][1] = r1;
            bh[2 * nt2 + 1][0] = r2; bh[2 * nt2 + 1][1] = r3;
            ldmx4t(r0, r1, r2, r3, uBlo + off);
            bl[2 * nt2][0] = r0; bl[2 * nt2][1] = r1;
            bl[2 * nt2 + 1][0] = r2; bl[2 * nt2 + 1][1] = r3;
        }
        #pragma unroll
        for (int mt = 0; mt < 2; ++mt)
            #pragma unroll
            for (int nt = 0; nt < 4; ++nt) {
                mma_bf16(acc[mt][nt], ah[mt][0], ah[mt][1], ah[mt][2], ah[mt][3],
                         bh[nt][0], bh[nt][1]);
                mma_bf16(acc[mt][nt], ah[mt][0], ah[mt][1], ah[mt][2], ah[mt][3],
                         bl[nt][0], bl[nt][1]);
                mma_bf16(acc[mt][nt], al[mt][0], al[mt][1], al[mt][2], al[mt][3],
                         bh[nt][0], bh[nt][1]);
            }
    }
}

// ---------------------------------------------------------------------------
// FUSED bias kernel: 128-row tile, 512 threads, warps 4(M)x4(N).
// Phase 0: acc  = init_messages @ W_i           (K=165, pad 176)
//          -> msg0 = relu(acc)  [inp], written mid-kernel
// Phase 1: acc += attdiff @ W_h[128:]           (K=151, pad 160)
//          -> bias = acc
// ---------------------------------------------------------------------------
__global__ void __launch_bounds__(512, 1) k_bias(
    const float* __restrict__ A0,     const float* __restrict__ attnei,
    const float* __restrict__ attfea, const float* __restrict__ Wi,
    const float* __restrict__ Wh_att, const int* __restrict__ b2a,
    const int* __restrict__ b2revb,
    float* __restrict__ bias_out, float* __restrict__ msg_out)
{
    constexpr int PITCHA = 384;
    constexpr int K0 = 176, K1 = 160;     // padded Ks

    extern __shared__ char sm[];
    char* pAhi = sm;                       // 128*384
    char* pAlo = sm + 128 * PITCHA;
    char* pBhi = sm + 2 * 128 * PITCHA;    // K0*256 max
    char* pBlo = pBhi + K0 * 256;
    const u32 uAhi = smem_u32(pAhi);
    const u32 uAlo = smem_u32(pAlo);
    const u32 uBhi = smem_u32(pBhi);
    const u32 uBlo = smem_u32(pBlo);

    const int tid  = threadIdx.x;
    const int lane = tid & 31;
    const int warp = tid >> 5;
    const int wm   = warp & 3;
    const int wn   = warp >> 2;
    const long row0 = (long)blockIdx.x * 128;

    float acc[2][4][4];
    #pragma unroll
    for (int mt = 0; mt < 2; ++mt)
        #pragma unroll
        for (int nt = 0; nt < 4; ++nt)
            #pragma unroll
            for (int e = 0; e < 4; ++e) acc[mt][nt][e] = 0.f;

    const int gr = lane >> 2;
    const int gc = (lane & 3) * 2;

    // ================= Phase 0: init_messages @ W_i =================
    fill_B(Wi, K0, DMSG, pBhi, pBlo, tid, 512);
    {
        const int r = tid >> 2, h = tid & 3;
        const long b = row0 + r;
        const bool valid = b < NBb;
        const float* pA = A0 + (long)(valid ? b : 0) * DMSG;
        for (int q = h; q < K0 / 8; q += 4) {
            float v[8];
            #pragma unroll
            for (int t = 0; t < 8; ++t) {
                int c = q * 8 + t;
                v[t] = (valid && c < DMSG) ? pA[c] : 0.f;
            }
            u32 hi[4], lo[4];
            cvt8(v, hi, lo);
            int sw = (q ^ (r & 7)) * 16;
            *(uint4*)(pAhi + r * PITCHA + sw) = make_uint4(hi[0], hi[1], hi[2], hi[3]);
            *(uint4*)(pAlo + r * PITCHA + sw) = make_uint4(lo[0], lo[1], lo[2], lo[3]);
        }
    }
    __syncthreads();
    mma_loop<PITCHA>(K0 / 16, uAhi, uAlo, uBhi, uBlo, acc, lane, wm, wn);

    // msg0 = relu(inp): write phase-0 partial now
    #pragma unroll
    for (int mt = 0; mt < 2; ++mt)
        #pragma unroll
        for (int nt = 0; nt < 4; ++nt) {
            long r1 = row0 + wm * 32 + mt * 16 + gr;
            long r2 = r1 + 8;
            int  c  = wn * 32 + nt * 8 + gc;
            const float* a = acc[mt][nt];
            if (r1 < NBb)
                *(float2*)(msg_out + (size_t)r1 * HH + c) =
                    make_float2(fmaxf(a[0], 0.f), fmaxf(a[1], 0.f));
            if (r2 < NBb)
                *(float2*)(msg_out + (size_t)r2 * HH + c) =
                    make_float2(fmaxf(a[2], 0.f), fmaxf(a[3], 0.f));
        }
    __syncthreads();   // mainloop + stores done before smem refill

    // ================= Phase 1: attdiff @ W_h[128:] =================
    fill_B(Wh_att, K1, DATT, pBhi, pBlo, tid, 512);
    {
        const int r = tid >> 2, h = tid & 3;
        const long b = row0 + r;
        const bool valid = b < NBb;
        const long bc = valid ? b : 0;
        int ia = b2a[bc];
        int ir = b2a[b2revb[bc]];
        const float* pA = attnei + (long)ia * DATT;
        const float* pR = attfea + (long)ir * DATT;
        for (int q = h; q < K1 / 8; q += 4) {
            float v[8];
            #pragma unroll
            for (int t = 0; t < 8; ++t) {
                int c = q * 8 + t;
                v[t] = (valid && c < DATT) ? (pA[c] - pR[c]) : 0.f;
            }
            u32 hi[4], lo[4];
            cvt8(v, hi, lo);
            int sw = (q ^ (r & 7)) * 16;
            *(uint4*)(pAhi + r * PITCHA + sw) = make_uint4(hi[0], hi[1], hi[2], hi[3]);
            *(uint4*)(pAlo + r * PITCHA + sw) = make_uint4(lo[0], lo[1], lo[2], lo[3]);
        }
    }
    __syncthreads();
    mma_loop<PITCHA>(K1 / 16, uAhi, uAlo, uBhi, uBlo, acc, lane, wm, wn);

    // bias = acc
    #pragma unroll
    for (int mt = 0; mt < 2; ++mt)
        #pragma unroll
        for (int nt = 0; nt < 4; ++nt) {
            long r1 = row0 + wm * 32 + mt * 16 + gr;
            long r2 = r1 + 8;
            int  c  = wn * 32 + nt * 8 + gc;
            const float* a = acc[mt][nt];
            if (r1 < NBb)
                *(float2*)(bias_out + (size_t)r1 * HH + c) = make_float2(a[0], a[1]);
            if (r2 < NBb)
                *(float2*)(bias_out + (size_t)r2 * HH + c) = make_float2(a[2], a[3]);
        }
}

// ---------------------------------------------------------------------------
// MSG GEMM: 64-row tile, 256 threads, 8 warps (2M x 4N), smem 96KB -> 2 CTA/SM.
// msg_out = relu(bias + (nei[b2a] - msg_in[b2revb]) @ W_h[:128]),  K = 128.
// ---------------------------------------------------------------------------
__global__ void __launch_bounds__(256, 2) k_msg(
    const float* __restrict__ nei, const float* __restrict__ msg_in,
    const float* __restrict__ Wh, const int* __restrict__ b2a,
    const int* __restrict__ b2revb, const float* __restrict__ bias,
    float* __restrict__ msg_out)
{
    constexpr int PITCHA = 256;           // 128 bf16 cols
    constexpr int KP = 128;

    extern __shared__ char sm[];
    char* pAhi = sm;                       // 64*256
    char* pAlo = sm + 64 * PITCHA;
    char* pBhi = sm + 2 * 64 * PITCHA;     // 128*256
    char* pBlo = pBhi + KP * 256;
    const u32 uAhi = smem_u32(pAhi);
    const u32 uAlo = smem_u32(pAlo);
    const u32 uBhi = smem_u32(pBhi);
    const u32 uBlo = smem_u32(pBlo);

    const int tid  = threadIdx.x;
    const int lane = tid & 31;
    const int warp = tid >> 5;
    const int wm   = warp & 1;            // rows wm*32
    const int wn   = warp >> 1;           // cols wn*32
    const long row0 = (long)blockIdx.x * 64;

    // ---- B fill: thread = half k-row (8 chunks) ----
    {
        const int k = tid >> 1, h2 = tid & 1;
        const float* wr = Wh + (long)k * HH;
        #pragma unroll
        for (int q = 8 * h2; q < 8 * h2 + 8; ++q) {
            float v[8];
            float4 x0 = ((const float4*)wr)[2 * q];
            float4 x1 = ((const float4*)wr)[2 * q + 1];
            v[0] = x0.x; v[1] = x0.y; v[2] = x0.z; v[3] = x0.w;
            v[4] = x1.x; v[5] = x1.y; v[6] = x1.z; v[7] = x1.w;
            u32 hi[4], lo[4];
            cvt8(v, hi, lo);
            int sw = (q ^ (k & 7)) * 16;
            *(uint4*)(pBhi + k * 256 + sw) = make_uint4(hi[0], hi[1], hi[2], hi[3]);
            *(uint4*)(pBlo + k * 256 + sw) = make_uint4(lo[0], lo[1], lo[2], lo[3]);
        }
    }

    // ---- A fill: gather + subtract + split; thread = quarter row ----
    {
        const int r = tid >> 2, h = tid & 3;
        const long b = row0 + r;
        const bool valid = b < NBb;
        const long bc = valid ? b : 0;
        int ia = b2a[bc];
        int ib = b2revb[bc];
        const float* pA = nei + (long)ia * HH;
        const float* pR = msg_in + (long)ib * HH;

        #pragma unroll
        for (int q = h; q < 16; q += 4) {
            float v[8];
            float4 x0 = ((const float4*)pA)[2 * q];
            float4 x1 = ((const float4*)pA)[2 * q + 1];
            float4 y0 = ((const float4*)pR)[2 * q];
            float4 y1 = ((const float4*)pR)[2 * q + 1];
            v[0] = x0.x - y0.x; v[1] = x0.y - y0.y;
            v[2] = x0.z - y0.z; v[3] = x0.w - y0.w;
            v[4] = x1.x - y1.x; v[5] = x1.y - y1.y;
            v[6] = x1.z - y1.z; v[7] = x1.w - y1.w;
            if (!valid) {
                #pragma unroll
                for (int t = 0; t < 8; ++t) v[t] = 0.f;
            }
            u32 hi[4], lo[4];
            cvt8(v, hi, lo);
            int sw = (q ^ (r & 7)) * 16;
            *(uint4*)(pAhi + r * PITCHA + sw) = make_uint4(hi[0], hi[1], hi[2], hi[3]);
            *(uint4*)(pAlo + r * PITCHA + sw) = make_uint4(lo[0], lo[1], lo[2], lo[3]);
        }
    }
    __syncthreads();

    float acc[2][4][4];
    #pragma unroll
    for (int mt = 0; mt < 2; ++mt)
        #pragma unroll
        for (int nt = 0; nt < 4; ++nt)
            #pragma unroll
            for (int e = 0; e < 4; ++e) acc[mt][nt][e] = 0.f;

    mma_loop<PITCHA>(KP / 16, uAhi, uAlo, uBhi, uBlo, acc, lane, wm, wn);

    // ---- Epilogue: bias + relu ----
    const int gr = lane >> 2;
    const int gc = (lane & 3) * 2;
    #pragma unroll
    for (int mt = 0; mt < 2; ++mt)
        #pragma unroll
        for (int nt = 0; nt < 4; ++nt) {
            long r1 = row0 + wm * 32 + mt * 16 + gr;
            long r2 = r1 + 8;
            int  c  = wn * 32 + nt * 8 + gc;
            const float* a = acc[mt][nt];
            if (r1 < NBb) {
                size_t o = (size_t)r1 * HH + c;
                float2 b = *(const float2*)(bias + o);
                *(float2*)(msg_out + o) = make_float2(fmaxf(b.x + a[0], 0.f),
                                                      fmaxf(b.y + a[1], 0.f));
            }
            if (r2 < NBb) {
                size_t o = (size_t)r2 * HH + c;
                float2 b = *(const float2*)(bias + o);
                *(float2*)(msg_out + o) = make_float2(fmaxf(b.x + a[2], 0.f),
                                                      fmaxf(b.y + a[3], 0.f));
            }
        }
}

// ---------------------------------------------------------------------------
// Aggregation kernels (DRAM-bound)
// ---------------------------------------------------------------------------
__global__ void __launch_bounds__(256) k_att_agg(
    const float* __restrict__ attfea, const int* __restrict__ a2att,
    float* __restrict__ attnei)
{
    const int warp = threadIdx.x >> 5, lane = threadIdx.x & 31;
    const int a = blockIdx.x * 8 + warp;
    if (a >= NAa) return;
    int idx[6];
    #pragma unroll
    for (int j = 0; j < 6; ++j) idx[j] = a2att[a * 6 + j];
    float acc[5] = {0.f, 0.f, 0.f, 0.f, 0.f};
    #pragma unroll
    for (int j = 0; j < 6; ++j) {
        const float* p = attfea + (long)idx[j] * DATT;
        #pragma unroll
        for (int t = 0; t < 5; ++t) {
            int c = t * 32 + lane;
            if (c < DATT) acc[t] += p[c];
        }
    }
    float* o = attnei + (long)a * DATT;
    #pragma unroll
    for (int t = 0; t < 5; ++t) {
        int c = t * 32 + lane;
        if (c < DATT) o[c] = acc[t];
    }
}

__global__ void __launch_bounds__(256) k_nei_agg(
    const float* __restrict__ msg, const int* __restrict__ a2nei,
    float* __restrict__ nei)
{
    const int warp = threadIdx.x >> 5, lane = threadIdx.x & 31;
    const int a = blockIdx.x * 8 + warp;
    if (a >= NAa) return;
    int idx[6];
    #pragma unroll
    for (int j = 0; j < 6; ++j) idx[j] = a2nei[a * 6 + j];
    float4 acc = make_float4(0.f, 0.f, 0.f, 0.f);
    #pragma unroll
    for (int j = 0; j < 6; ++j) {
        float4 v = *(const float4*)(msg + (long)idx[j] * HH + lane * 4);
        acc.x += v.x; acc.y += v.y; acc.z += v.z; acc.w += v.w;
    }
    *(float4*)(nei + (long)a * HH + lane * 4) = acc;
}

// Dummy: keeps ncu (-s 5 -c 1) aligned so launch #6 is k_msg.
__global__ void k_dummy(float* p) { if (threadIdx.x == 0) p[0] = 0.f; }

// ---------------------------------------------------------------------------
extern "C" void kernel_launch(void* const* d_in, const int* in_sizes, int n_in,
                              void* d_out, int out_size) {
    (void)in_sizes; (void)n_in; (void)out_size;

    const float* init_messages = (const float*)d_in[0];
    const float* attfea        = (const float*)d_in[1];
    const float* W_i           = (const float*)d_in[2];
    const float* W_h           = (const float*)d_in[3];  // [279][128]
    const int*   a2nei         = (const int*)d_in[4];
    const int*   a2att         = (const int*)d_in[5];
    const int*   b2a           = (const int*)d_in[6];
    const int*   b2revb        = (const int*)d_in[7];
    float*       out           = (float*)d_out;

    constexpr int SM_BIAS = 2 * (128 * 384) + 2 * (176 * 256);  // 188416
    constexpr int SM_MSG  = 2 * (64 * 256) + 2 * (128 * 256);   // 98304

    cudaFuncSetAttribute(k_bias, cudaFuncAttributeMaxDynamicSharedMemorySize, SM_BIAS);
    cudaFuncSetAttribute(k_msg,  cudaFuncAttributeMaxDynamicSharedMemorySize, SM_MSG);

    float *bias, *m0, *m1, *nei, *attnei;
    cudaGetSymbolAddress((void**)&bias,   g_bias2);
    cudaGetSymbolAddress((void**)&m0,     g_msg0);
    cudaGetSymbolAddress((void**)&m1,     g_msg1);
    cudaGetSymbolAddress((void**)&nei,    g_nei);
    cudaGetSymbolAddress((void**)&attnei, g_attnei);

    const int gb128 = (NBb + 127) / 128;  // 3907
    const int gb64  = (NBb + 63) / 64;    // 7813
    const int ga    = NAa / 8;            // 31250

    k_dummy<<<1, 32>>>(nei);                                     // 1

    k_att_agg<<<ga, 256>>>(attfea, a2att, attnei);               // 2
    k_bias<<<gb128, 512, SM_BIAS>>>(init_messages, attnei, attfea,
                                    W_i, W_h + HH * HH,
                                    b2a, b2revb, bias, m0);      // 3

    k_dummy<<<1, 32>>>(nei);                                     // 4

    float* cur = m0;
    float* nxt = m1;
    for (int it = 0; it < 5; ++it) {
        k_nei_agg<<<ga, 256>>>(cur, a2nei, nei);                 // 5, 7, ...
        float* o = (it == 4) ? out : nxt;
        k_msg<<<gb64, 256, SM_MSG>>>(nei, cur, W_h, b2a, b2revb, bias, o);  // 6 <- profiled
        float* t = cur; cur = nxt; nxt = t;
    }
}

// round 12
// speedup vs baseline: 3.2736x; 1.2306x over previous
#include <cuda_runtime.h>
#include <cstdint>

// ---------------------------------------------------------------------------
// MPNEncoder, DEPTH=6, H=128 — bf16 hi/lo split GEMMs on legacy HMMA
// (mma.sync.m16n8k16.bf16; tcgen05 is PTX-gated off under compute_103).
//
//   attnei[a]  = sum_j attfea[a2attached[a,j]]             (once)
//   k_bias (fused, 2 phases sharing fp32 accum):
//     phase0: acc  = init_messages @ W_i ; msg0 = relu(acc)
//     phase1: acc += (attnei[b2a]-attfea[b2a_rev]) @ W_h[128:] ; bias = acc
//   5x: nei[a] = sum_j msg[a2nei[a,j]]
//       msg    = relu(bias + (nei[b2a] - msg[b2revb]) @ W_h[:128])
//
// R11: B planes (bf16 hi/lo, swizzled smem-image layout) are precomputed ONCE
// into a __device__ global by prep blocks folded into the k_att_agg launch;
// per-CTA B fill is a cp.async 16B copy overlapped with the A gather.
// ---------------------------------------------------------------------------

constexpr int NBb  = 500000;
constexpr int NAa  = 250000;
constexpr int DMSG = 165;
constexpr int DATT = 151;
constexpr int HH   = 128;

// B image rows: Wi padded 176, Wh_att padded 160, Wh_msg 128  (hi||lo each)
constexpr int K_WI  = 176;
constexpr int K_ATT = 160;
constexpr int K_MSG = 128;
constexpr int BROWS = K_WI + K_ATT + K_MSG;          // 464

__device__ float g_bias2 [(size_t)NBb * HH];
__device__ float g_msg0  [(size_t)NBb * HH];
__device__ float g_msg1  [(size_t)NBb * HH];
__device__ float g_nei   [(size_t)NAa * HH];
__device__ float g_attnei[(size_t)NAa * DATT];
__device__ uint4 g_B     [BROWS * 32];               // 464*512 bytes

typedef unsigned int u32;

__device__ __forceinline__ u32 smem_u32(const void* p) {
    u32 a;
    asm("{ .reg .u64 t; cvta.to.shared.u64 t, %1; cvt.u32.u64 %0, t; }"
        : "=r"(a) : "l"(p));
    return a;
}
__device__ __forceinline__ void ldmx4(u32& r0, u32& r1, u32& r2, u32& r3, u32 addr) {
    asm volatile("ldmatrix.sync.aligned.m8n8.x4.shared.b16 {%0,%1,%2,%3}, [%4];"
                 : "=r"(r0), "=r"(r1), "=r"(r2), "=r"(r3) : "r"(addr));
}
__device__ __forceinline__ void ldmx4t(u32& r0, u32& r1, u32& r2, u32& r3, u32 addr) {
    asm volatile("ldmatrix.sync.aligned.m8n8.x4.trans.shared.b16 {%0,%1,%2,%3}, [%4];"
                 : "=r"(r0), "=r"(r1), "=r"(r2), "=r"(r3) : "r"(addr));
}
__device__ __forceinline__ void mma_bf16(float (&d)[4],
                                         u32 a0, u32 a1, u32 a2, u32 a3,
                                         u32 b0, u32 b1) {
    asm volatile("mma.sync.aligned.m16n8k16.row.col.f32.bf16.bf16.f32 "
                 "{%0,%1,%2,%3}, {%4,%5,%6,%7}, {%8,%9}, {%0,%1,%2,%3};"
                 : "+f"(d[0]), "+f"(d[1]), "+f"(d[2]), "+f"(d[3])
                 : "r"(a0), "r"(a1), "r"(a2), "r"(a3), "r"(b0), "r"(b1));
}
__device__ __forceinline__ void cpasync16(u32 dst, const void* src) {
    asm volatile("cp.async.cg.shared.global [%0], [%1], 16;"
                 :: "r"(dst), "l"(src));
}
__device__ __forceinline__ void cpasync_wait() {
    asm volatile("cp.async.commit_group;\ncp.async.wait_group 0;" ::: "memory");
}

// 8 floats -> 4 hi bf16x2 regs + 4 lo bf16x2 regs (low half = even index)
__device__ __forceinline__ void cvt8(const float* v, u32* hi, u32* lo) {
    #pragma unroll
    for (int i = 0; i < 4; ++i) {
        u32 u0 = __float_as_uint(v[2 * i])     & 0xffff0000u;
        u32 u1 = __float_as_uint(v[2 * i + 1]) & 0xffff0000u;
        hi[i] = u1 | (u0 >> 16);
        float l0 = v[2 * i]     - __uint_as_float(u0);
        float l1 = v[2 * i + 1] - __uint_as_float(u1);
        asm("cvt.rn.bf16x2.f32 %0, %1, %2;" : "=r"(lo[i]) : "f"(l1), "f"(l0));
    }
}

// Shared MMA mainloop (warp tile 32x32, mt=2, nt=4), full unroll over NK.
template<int PITCHA, int NK>
__device__ __forceinline__ void mma_loop(
    u32 uAhi, u32 uAlo, u32 uBhi, u32 uBlo,
    float (&acc)[2][4][4], int lane, int wm, int wn)
{
    const int aj   = lane >> 3;
    const int ai   = lane & 7;
    const int ajk  = aj >> 1;
    const int ajr  = (aj & 1) * 8;
    const int bkl  = lane & 15;
    const int bchl = lane >> 4;

    #pragma unroll 2
    for (int ks = 0; ks < NK; ++ks) {
        u32 ah[2][4], al[2][4];
        #pragma unroll
        for (int mt = 0; mt < 2; ++mt) {
            int arow = wm * 32 + mt * 16 + ajr + ai;
            int ch   = 2 * ks + ajk;
            u32 off  = (u32)(arow * PITCHA) + (u32)((ch ^ (arow & 7)) << 4);
            ldmx4(ah[mt][0], ah[mt][1], ah[mt][2], ah[mt][3], uAhi + off);
            ldmx4(al[mt][0], al[mt][1], al[mt][2], al[mt][3], uAlo + off);
        }
        u32 bh[4][2], bl[4][2];
        #pragma unroll
        for (int nt2 = 0; nt2 < 2; ++nt2) {
            int krow = ks * 16 + bkl;
            int ch   = wn * 4 + nt2 * 2 + bchl;
            u32 off  = (u32)(krow * 256) + (u32)((ch ^ (krow & 7)) << 4);
            u32 r0, r1, r2, r3;
            ldmx4t(r0, r1, r2, r3, uBhi + off);
            bh[2 * nt2][0] = r0; bh[2 * nt2][1] = r1;
            bh[2 * nt2 + 1][0] = r2; bh[2 * nt2 + 1][1] = r3;
            ldmx4t(r0, r1, r2, r3, uBlo + off);
            bl[2 * nt2][0] = r0; bl[2 * nt2][1] = r1;
            bl[2 * nt2 + 1][0] = r2; bl[2 * nt2 + 1][1] = r3;
        }
        #pragma unroll
        for (int mt = 0; mt < 2; ++mt)
            #pragma unroll
            for (int nt = 0; nt < 4; ++nt) {
                mma_bf16(acc[mt][nt], ah[mt][0], ah[mt][1], ah[mt][2], ah[mt][3],
                         bh[nt][0], bh[nt][1]);
                mma_bf16(acc[mt][nt], ah[mt][0], ah[mt][1], ah[mt][2], ah[mt][3],
                         bl[nt][0], bl[nt][1]);
                mma_bf16(acc[mt][nt], al[mt][0], al[mt][1], al[mt][2], al[mt][3],
                         bh[nt][0], bh[nt][1]);
            }
    }
}

// ---------------------------------------------------------------------------
// k_att_agg + B-plane prep (extra blocks).  Launch grid = GA + PREP_BLOCKS.
// ---------------------------------------------------------------------------
constexpr int GA = NAa / 8;                              // 31250
constexpr int PREP_ITEMS  = BROWS * 16;                  // (k,q) pairs
constexpr int PREP_BLOCKS = (PREP_ITEMS + 255) / 256;    // 29

__global__ void __launch_bounds__(256) k_att_agg(
    const float* __restrict__ attfea, const int* __restrict__ a2att,
    float* __restrict__ attnei,
    const float* __restrict__ W_i, const float* __restrict__ W_h)
{
    if (blockIdx.x >= GA) {
        // ---- B-plane prep: split + swizzle weights into g_B ----
        int idx = (blockIdx.x - GA) * 256 + threadIdx.x;
        if (idx >= PREP_ITEMS) return;
        int r = idx >> 4, q = idx & 15;
        const float* src; unsigned char* dst; int k, Ksz, Kact;
        unsigned char* gb = (unsigned char*)g_B;
        if (r < K_WI) {
            k = r;           Ksz = K_WI;  Kact = DMSG; src = W_i;           dst = gb;
        } else if (r < K_WI + K_ATT) {
            k = r - K_WI;    Ksz = K_ATT; Kact = DATT; src = W_h + HH * HH; dst = gb + K_WI * 512;
        } else {
            k = r - K_WI - K_ATT; Ksz = K_MSG; Kact = HH; src = W_h;        dst = gb + (K_WI + K_ATT) * 512;
        }
        float v[8];
        #pragma unroll
        for (int t = 0; t < 8; ++t) {
            int c = q * 8 + t;
            v[t] = (k < Kact) ? src[(long)k * HH + c] : 0.f;
        }
        u32 hi[4], lo[4];
        cvt8(v, hi, lo);
        int sw = (q ^ (k & 7)) * 16;
        *(uint4*)(dst + k * 256 + sw)             = make_uint4(hi[0], hi[1], hi[2], hi[3]);
        *(uint4*)(dst + Ksz * 256 + k * 256 + sw) = make_uint4(lo[0], lo[1], lo[2], lo[3]);
        return;
    }

    const int warp = threadIdx.x >> 5, lane = threadIdx.x & 31;
    const int a = blockIdx.x * 8 + warp;
    if (a >= NAa) return;
    int idx[6];
    #pragma unroll
    for (int j = 0; j < 6; ++j) idx[j] = a2att[a * 6 + j];
    float acc[5] = {0.f, 0.f, 0.f, 0.f, 0.f};
    #pragma unroll
    for (int j = 0; j < 6; ++j) {
        const float* p = attfea + (long)idx[j] * DATT;
        #pragma unroll
        for (int t = 0; t < 5; ++t) {
            int c = t * 32 + lane;
            if (c < DATT) acc[t] += p[c];
        }
    }
    float* o = attnei + (long)a * DATT;
    #pragma unroll
    for (int t = 0; t < 5; ++t) {
        int c = t * 32 + lane;
        if (c < DATT) o[c] = acc[t];
    }
}

// ---------------------------------------------------------------------------
// FUSED bias kernel: 128-row tile, 512 threads, warps 4(M)x4(N).
// ---------------------------------------------------------------------------
__global__ void __launch_bounds__(512, 1) k_bias(
    const float* __restrict__ A0,     const float* __restrict__ attnei,
    const float* __restrict__ attfea, const int* __restrict__ b2a,
    const int* __restrict__ b2revb,
    float* __restrict__ bias_out, float* __restrict__ msg_out)
{
    constexpr int PITCHA = 384;

    extern __shared__ char sm[];
    char* pAhi = sm;                       // 128*384
    char* pAlo = sm + 128 * PITCHA;
    char* pBhi = sm + 2 * 128 * PITCHA;    // up to K_WI*512
    const u32 uAhi = smem_u32(pAhi);
    const u32 uAlo = smem_u32(pAlo);
    const u32 uBhi = smem_u32(pBhi);

    const int tid  = threadIdx.x;
    const int lane = tid & 31;
    const int warp = tid >> 5;
    const int wm   = warp & 3;
    const int wn   = warp >> 2;
    const long row0 = (long)blockIdx.x * 128;
    const unsigned char* gb = (const unsigned char*)g_B;

    float acc[2][4][4];
    #pragma unroll
    for (int mt = 0; mt < 2; ++mt)
        #pragma unroll
        for (int nt = 0; nt < 4; ++nt)
            #pragma unroll
            for (int e = 0; e < 4; ++e) acc[mt][nt][e] = 0.f;

    const int gr = lane >> 2;
    const int gc = (lane & 3) * 2;

    // ================= Phase 0: init_messages @ W_i (K=176) =================
    // B copy via cp.async (176*512 B = 5632 u4; 11 per thread), then A fill.
    #pragma unroll
    for (int i = 0; i < 11; ++i) {
        int e = tid + i * 512;
        if (e < K_WI * 32) cpasync16(uBhi + e * 16, gb + e * 16);
    }
    {
        const int r = tid >> 2, h = tid & 3;
        const long b = row0 + r;
        const bool valid = b < NBb;
        const float* pA = A0 + (long)(valid ? b : 0) * DMSG;
        for (int q = h; q < K_WI / 8; q += 4) {
            float v[8];
            #pragma unroll
            for (int t = 0; t < 8; ++t) {
                int c = q * 8 + t;
                v[t] = (valid && c < DMSG) ? pA[c] : 0.f;
            }
            u32 hi[4], lo[4];
            cvt8(v, hi, lo);
            int sw = (q ^ (r & 7)) * 16;
            *(uint4*)(pAhi + r * PITCHA + sw) = make_uint4(hi[0], hi[1], hi[2], hi[3]);
            *(uint4*)(pAlo + r * PITCHA + sw) = make_uint4(lo[0], lo[1], lo[2], lo[3]);
        }
    }
    cpasync_wait();
    __syncthreads();
    mma_loop<PITCHA, K_WI / 16>(uAhi, uAlo, uBhi, uBhi + K_WI * 256,
                                acc, lane, wm, wn);

    // msg0 = relu(inp)
    #pragma unroll
    for (int mt = 0; mt < 2; ++mt)
        #pragma unroll
        for (int nt = 0; nt < 4; ++nt) {
            long r1 = row0 + wm * 32 + mt * 16 + gr;
            long r2 = r1 + 8;
            int  c  = wn * 32 + nt * 8 + gc;
            const float* a = acc[mt][nt];
            if (r1 < NBb)
                *(float2*)(msg_out + (size_t)r1 * HH + c) =
                    make_float2(fmaxf(a[0], 0.f), fmaxf(a[1], 0.f));
            if (r2 < NBb)
                *(float2*)(msg_out + (size_t)r2 * HH + c) =
                    make_float2(fmaxf(a[2], 0.f), fmaxf(a[3], 0.f));
        }
    __syncthreads();

    // ================= Phase 1: attdiff @ W_h[128:] (K=160) =================
    #pragma unroll
    for (int i = 0; i < 10; ++i) {
        int e = tid + i * 512;
        if (e < K_ATT * 32) cpasync16(uBhi + e * 16, gb + K_WI * 512 + e * 16);
    }
    {
        const int r = tid >> 2, h = tid & 3;
        const long b = row0 + r;
        const bool valid = b < NBb;
        const long bc = valid ? b : 0;
        int ia = b2a[bc];
        int ir = b2a[b2revb[bc]];
        const float* pA = attnei + (long)ia * DATT;
        const float* pR = attfea + (long)ir * DATT;
        for (int q = h; q < K_ATT / 8; q += 4) {
            float v[8];
            #pragma unroll
            for (int t = 0; t < 8; ++t) {
                int c = q * 8 + t;
                v[t] = (valid && c < DATT) ? (pA[c] - pR[c]) : 0.f;
            }
            u32 hi[4], lo[4];
            cvt8(v, hi, lo);
            int sw = (q ^ (r & 7)) * 16;
            *(uint4*)(pAhi + r * PITCHA + sw) = make_uint4(hi[0], hi[1], hi[2], hi[3]);
            *(uint4*)(pAlo + r * PITCHA + sw) = make_uint4(lo[0], lo[1], lo[2], lo[3]);
        }
    }
    cpasync_wait();
    __syncthreads();
    mma_loop<PITCHA, K_ATT / 16>(uAhi, uAlo, uBhi, uBhi + K_ATT * 256,
                                 acc, lane, wm, wn);

    // bias = acc
    #pragma unroll
    for (int mt = 0; mt < 2; ++mt)
        #pragma unroll
        for (int nt = 0; nt < 4; ++nt) {
            long r1 = row0 + wm * 32 + mt * 16 + gr;
            long r2 = r1 + 8;
            int  c  = wn * 32 + nt * 8 + gc;
            const float* a = acc[mt][nt];
            if (r1 < NBb)
                *(float2*)(bias_out + (size_t)r1 * HH + c) = make_float2(a[0], a[1]);
            if (r2 < NBb)
                *(float2*)(bias_out + (size_t)r2 * HH + c) = make_float2(a[2], a[3]);
        }
}

// ---------------------------------------------------------------------------
// MSG GEMM: 64-row tile, 256 threads, 8 warps (2M x 4N), smem 96KB, 2 CTA/SM.
// msg_out = relu(bias + (nei[b2a] - msg_in[b2revb]) @ W_h[:128]),  K = 128.
// ---------------------------------------------------------------------------
__global__ void __launch_bounds__(256, 2) k_msg(
    const float* __restrict__ nei, const float* __restrict__ msg_in,
    const int* __restrict__ b2a, const int* __restrict__ b2revb,
    const float* __restrict__ bias, float* __restrict__ msg_out)
{
    constexpr int PITCHA = 256;

    extern __shared__ char sm[];
    char* pAhi = sm;                       // 64*256
    char* pAlo = sm + 64 * PITCHA;
    char* pBhi = sm + 2 * 64 * PITCHA;     // 128*512 (hi||lo)
    const u32 uAhi = smem_u32(pAhi);
    const u32 uAlo = smem_u32(pAlo);
    const u32 uBhi = smem_u32(pBhi);

    const int tid  = threadIdx.x;
    const int lane = tid & 31;
    const int warp = tid >> 5;
    const int wm   = warp & 1;
    const int wn   = warp >> 1;
    const long row0 = (long)blockIdx.x * 64;
    const unsigned char* gb = (const unsigned char*)g_B + (K_WI + K_ATT) * 512;

    // ---- B copy via cp.async: 128*512 B = 4096 u4, 16/thread ----
    #pragma unroll
    for (int i = 0; i < 16; ++i) {
        int e = tid + i * 256;
        cpasync16(uBhi + e * 16, gb + e * 16);
    }

    // ---- A fill: gather + subtract + split; thread = quarter row ----
    {
        const int r = tid >> 2, h = tid & 3;
        const long b = row0 + r;
        const bool valid = b < NBb;
        const long bc = valid ? b : 0;
        int ia = b2a[bc];
        int ib = b2revb[bc];
        const float* pA = nei + (long)ia * HH;
        const float* pR = msg_in + (long)ib * HH;

        #pragma unroll
        for (int q = h; q < 16; q += 4) {
            float v[8];
            float4 x0 = ((const float4*)pA)[2 * q];
            float4 x1 = ((const float4*)pA)[2 * q + 1];
            float4 y0 = ((const float4*)pR)[2 * q];
            float4 y1 = ((const float4*)pR)[2 * q + 1];
            v[0] = x0.x - y0.x; v[1] = x0.y - y0.y;
            v[2] = x0.z - y0.z; v[3] = x0.w - y0.w;
            v[4] = x1.x - y1.x; v[5] = x1.y - y1.y;
            v[6] = x1.z - y1.z; v[7] = x1.w - y1.w;
            if (!valid) {
                #pragma unroll
                for (int t = 0; t < 8; ++t) v[t] = 0.f;
            }
            u32 hi[4], lo[4];
            cvt8(v, hi, lo);
            int sw = (q ^ (r & 7)) * 16;
            *(uint4*)(pAhi + r * PITCHA + sw) = make_uint4(hi[0], hi[1], hi[2], hi[3]);
            *(uint4*)(pAlo + r * PITCHA + sw) = make_uint4(lo[0], lo[1], lo[2], lo[3]);
        }
    }
    cpasync_wait();
    __syncthreads();

    float acc[2][4][4];
    #pragma unroll
    for (int mt = 0; mt < 2; ++mt)
        #pragma unroll
        for (int nt = 0; nt < 4; ++nt)
            #pragma unroll
            for (int e = 0; e < 4; ++e) acc[mt][nt][e] = 0.f;

    mma_loop<PITCHA, K_MSG / 16>(uAhi, uAlo, uBhi, uBhi + K_MSG * 256,
                                 acc, lane, wm, wn);

    // ---- Epilogue: bias + relu ----
    const int gr = lane >> 2;
    const int gc = (lane & 3) * 2;
    #pragma unroll
    for (int mt = 0; mt < 2; ++mt)
        #pragma unroll
        for (int nt = 0; nt < 4; ++nt) {
            long r1 = row0 + wm * 32 + mt * 16 + gr;
            long r2 = r1 + 8;
            int  c  = wn * 32 + nt * 8 + gc;
            const float* a = acc[mt][nt];
            if (r1 < NBb) {
                size_t o = (size_t)r1 * HH + c;
                float2 b = *(const float2*)(bias + o);
                *(float2*)(msg_out + o) = make_float2(fmaxf(b.x + a[0], 0.f),
                                                      fmaxf(b.y + a[1], 0.f));
            }
            if (r2 < NBb) {
                size_t o = (size_t)r2 * HH + c;
                float2 b = *(const float2*)(bias + o);
                *(float2*)(msg_out + o) = make_float2(fmaxf(b.x + a[2], 0.f),
                                                      fmaxf(b.y + a[3], 0.f));
            }
        }
}

// ---------------------------------------------------------------------------
__global__ void __launch_bounds__(256) k_nei_agg(
    const float* __restrict__ msg, const int* __restrict__ a2nei,
    float* __restrict__ nei)
{
    const int warp = threadIdx.x >> 5, lane = threadIdx.x & 31;
    const int a = blockIdx.x * 8 + warp;
    if (a >= NAa) return;
    int idx[6];
    #pragma unroll
    for (int j = 0; j < 6; ++j) idx[j] = a2nei[a * 6 + j];
    float4 acc = make_float4(0.f, 0.f, 0.f, 0.f);
    #pragma unroll
    for (int j = 0; j < 6; ++j) {
        float4 v = *(const float4*)(msg + (long)idx[j] * HH + lane * 4);
        acc.x += v.x; acc.y += v.y; acc.z += v.z; acc.w += v.w;
    }
    *(float4*)(nei + (long)a * HH + lane * 4) = acc;
}

// ---------------------------------------------------------------------------
extern "C" void kernel_launch(void* const* d_in, const int* in_sizes, int n_in,
                              void* d_out, int out_size) {
    (void)in_sizes; (void)n_in; (void)out_size;

    const float* init_messages = (const float*)d_in[0];
    const float* attfea        = (const float*)d_in[1];
    const float* W_i           = (const float*)d_in[2];
    const float* W_h           = (const float*)d_in[3];  // [279][128]
    const int*   a2nei         = (const int*)d_in[4];
    const int*   a2att         = (const int*)d_in[5];
    const int*   b2a           = (const int*)d_in[6];
    const int*   b2revb        = (const int*)d_in[7];
    float*       out           = (float*)d_out;

    constexpr int SM_BIAS = 2 * (128 * 384) + K_WI * 512;   // 188416
    constexpr int SM_MSG  = 2 * (64 * 256) + K_MSG * 512;   // 98304

    cudaFuncSetAttribute(k_bias, cudaFuncAttributeMaxDynamicSharedMemorySize, SM_BIAS);
    cudaFuncSetAttribute(k_msg,  cudaFuncAttributeMaxDynamicSharedMemorySize, SM_MSG);

    float *bias, *m0, *m1, *nei, *attnei;
    cudaGetSymbolAddress((void**)&bias,   g_bias2);
    cudaGetSymbolAddress((void**)&m0,     g_msg0);
    cudaGetSymbolAddress((void**)&m1,     g_msg1);
    cudaGetSymbolAddress((void**)&nei,    g_nei);
    cudaGetSymbolAddress((void**)&attnei, g_attnei);

    const int gb128 = (NBb + 127) / 128;  // 3907
    const int gb64  = (NBb + 63) / 64;    // 7813

    // Launch 1: att aggregation + B-plane prep (extra blocks)
    k_att_agg<<<GA + PREP_BLOCKS, 256>>>(attfea, a2att, attnei, W_i, W_h);
    // Launch 2: fused bias/inp kernel
    k_bias<<<gb128, 512, SM_BIAS>>>(init_messages, attnei, attfea,
                                    b2a, b2revb, bias, m0);

    // Launches 3..12: 5x (nei_agg, msg GEMM).  Launch #4 = first k_msg (ncu).
    float* cur = m0;
    float* nxt = m1;
    for (int it = 0; it < 5; ++it) {
        k_nei_agg<<<GA, 256>>>(cur, a2nei, nei);
        float* o = (it == 4) ? out : nxt;
        k_msg<<<gb64, 256, SM_MSG>>>(nei, cur, b2a, b2revb, bias, o);
        float* t = cur; cur = nxt; nxt = t;
    }
}